// round 4
// baseline (speedup 1.0000x reference)
#include <cuda_runtime.h>
#include <math.h>
#include <float.h>

#define G 8
#define NC (G*G*G)
#define MAXN 10016
#define MAXM 32768
#define KNN 16
#define NF 32
#define CAP 800             // 27-cell window capacity (avg ~527)
#define IDXMASK 0x7FFu      // 11 low mantissa bits carry the slot index

// ---- device scratch (allocation-free) ----
__device__ float4 g_sorted[MAXN];   // cell-ordered: (x,y,z, orig-idx bits)
__device__ float4 g_icov_o[MAXN];   // inverse covariances, ORIGINAL index order
__device__ int g_cnt[NC], g_start[NC + 1];
__device__ int g_qcnt[NC], g_qstart[NC + 1];
__device__ int g_gcell[MAXN], g_grank[MAXN];
__device__ int g_qcell[MAXM], g_qrank[MAXM];
__device__ int g_qorder[MAXM];

__device__ __forceinline__ int cell_coord(float v) {
    int c = (int)(v * (float)G);
    return min(G - 1, max(0, c));
}

__global__ void k_clear() {
    int i = blockIdx.x * blockDim.x + threadIdx.x;
    if (i < NC) { g_cnt[i] = 0; g_qcnt[i] = 0; }
}

// Pass 1 of prep: cell ids + in-cell ranks (atomic return value) + icov.
__global__ void k_hist(const float* __restrict__ means,
                       const float* __restrict__ logc, int N,
                       const float* __restrict__ coords, int M) {
    int i = blockIdx.x * blockDim.x + threadIdx.x;
    if (i < N) {
        int c = (cell_coord(means[3*i+2]) * G + cell_coord(means[3*i+1])) * G
                + cell_coord(means[3*i+0]);
        g_gcell[i] = c;
        g_grank[i] = atomicAdd(&g_cnt[c], 1);
        g_icov_o[i] = make_float4(expf(-logc[3*i]), expf(-logc[3*i+1]),
                                  expf(-logc[3*i+2]), 0.f);
    }
    if (i < M) {
        int c = (cell_coord(coords[3*i+2]) * G + cell_coord(coords[3*i+1])) * G
                + cell_coord(coords[3*i+0]);
        g_qcell[i] = c;
        g_qrank[i] = atomicAdd(&g_qcnt[c], 1);
    }
}

// shfl-based two-level exclusive scan of both 512-entry histograms
__global__ void k_scan() {
    __shared__ int ws[16];
    int t = threadIdx.x, lane = t & 31, w = t >> 5;

    int s = g_cnt[t];
    for (int o = 1; o < 32; o <<= 1) {
        int u = __shfl_up_sync(0xffffffffu, s, o);
        if (lane >= o) s += u;
    }
    if (lane == 31) ws[w] = s;
    __syncthreads();
    if (t < 32) {
        int v = (t < 16) ? ws[t] : 0;
        for (int o = 1; o < 16; o <<= 1) {
            int u = __shfl_up_sync(0xffffffffu, v, o);
            if (t >= o) v += u;
        }
        if (t < 16) ws[t] = v;
    }
    __syncthreads();
    g_start[t + 1] = (w ? ws[w - 1] : 0) + s;
    if (t == 0) g_start[0] = 0;
    __syncthreads();

    s = g_qcnt[t];
    for (int o = 1; o < 32; o <<= 1) {
        int u = __shfl_up_sync(0xffffffffu, s, o);
        if (lane >= o) s += u;
    }
    if (lane == 31) ws[w] = s;
    __syncthreads();
    if (t < 32) {
        int v = (t < 16) ? ws[t] : 0;
        for (int o = 1; o < 16; o <<= 1) {
            int u = __shfl_up_sync(0xffffffffu, v, o);
            if (t >= o) v += u;
        }
        if (t < 16) ws[t] = v;
    }
    __syncthreads();
    g_qstart[t + 1] = (w ? ws[w - 1] : 0) + s;
    if (t == 0) g_qstart[0] = 0;
}

// Atomic-free scatter using precomputed (cell, rank).
__global__ void k_scatter(const float* __restrict__ means, int N, int M) {
    int i = blockIdx.x * blockDim.x + threadIdx.x;
    if (i < N) {
        int pos = g_start[g_gcell[i]] + g_grank[i];
        g_sorted[pos] = make_float4(means[3*i], means[3*i+1], means[3*i+2],
                                    __int_as_float(i));
    }
    if (i < M) {
        int pos = g_qstart[g_qcell[i]] + g_qrank[i];
        g_qorder[pos] = i;
    }
}

// Exact per-query fallback (rare): gmem ring expansion + threshold rescan.
__device__ __noinline__ void fallback_query(int q, float qx, float qy, float qz,
                                            int cx, int cy, int cz,
                                            const float4* __restrict__ feats4,
                                            float* __restrict__ out) {
    const float h = 1.0f / (float)G;
    float bd[KNN];
#pragma unroll
    for (int t = 0; t < KNN; t++) bd[t] = FLT_MAX;

    int rfin = 1;
    for (int r = 1; r <= G; ++r) {
        rfin = r;
        for (int dz = -r; dz <= r; ++dz) {
            int z = cz + dz; if ((unsigned)z >= G) continue;
            for (int dy = -r; dy <= r; ++dy) {
                int y = cy + dy; if ((unsigned)y >= G) continue;
                bool edge = (dz == -r) | (dz == r) | (dy == -r) | (dy == r);
                int step = (r > 1 && !edge) ? 2 * r : 1;
                for (int dx = -r; dx <= r; dx += step) {
                    int x = cx + dx; if ((unsigned)x >= G) continue;
                    int cid = (z * G + y) * G + x;
                    int c0 = g_start[cid], c1 = g_start[cid + 1];
                    for (int c = c0; c < c1; ++c) {
                        float4 g = g_sorted[c];
                        float ddx = qx - g.x, ddy = qy - g.y, ddz = qz - g.z;
                        float d2 = fmaf(ddx, ddx, fmaf(ddy, ddy, ddz * ddz));
                        if (d2 < bd[0]) {
                            bd[0] = d2;
#pragma unroll
                            for (int t = 0; t < KNN - 1; t++) {
                                float a = fmaxf(bd[t], bd[t+1]);
                                float b = fminf(bd[t], bd[t+1]);
                                bd[t] = a; bd[t+1] = b;
                            }
                        }
                    }
                }
            }
        }
        float m = 1e30f;
        if (cx - r > 0)     m = fminf(m, qx - (float)(cx - r) * h);
        if (cx + r < G - 1) m = fminf(m, (float)(cx + r + 1) * h - qx);
        if (cy - r > 0)     m = fminf(m, qy - (float)(cy - r) * h);
        if (cy + r < G - 1) m = fminf(m, (float)(cy + r + 1) * h - qy);
        if (cz - r > 0)     m = fminf(m, qz - (float)(cz - r) * h);
        if (cz + r < G - 1) m = fminf(m, (float)(cz + r + 1) * h - qz);
        if (bd[0] <= m * m) break;
    }
    const float T = bd[0];

    int myp[KNN];
#pragma unroll
    for (int t = 0; t < KNN; t++) myp[t] = 0;
    int cnt = 0;
    {
        const int r = rfin;
        for (int dz = -r; dz <= r; ++dz) {
            int z = cz + dz; if ((unsigned)z >= G) continue;
            for (int dy = -r; dy <= r; ++dy) {
                int y = cy + dy; if ((unsigned)y >= G) continue;
                for (int dx = -r; dx <= r; ++dx) {
                    int x = cx + dx; if ((unsigned)x >= G) continue;
                    int cid = (z * G + y) * G + x;
                    int c0 = g_start[cid], c1 = g_start[cid + 1];
                    for (int c = c0; c < c1; ++c) {
                        float4 g = g_sorted[c];
                        float ddx = qx - g.x, ddy = qy - g.y, ddz = qz - g.z;
                        float d2 = fmaf(ddx, ddx, fmaf(ddy, ddy, ddz * ddz));
                        if (d2 <= T && cnt < KNN) { myp[cnt] = c; cnt++; }
                    }
                }
            }
        }
    }

    float acc[NF];
#pragma unroll
    for (int f = 0; f < NF; f++) acc[f] = 0.f;
    float wsum = 0.f;
#pragma unroll
    for (int t = 0; t < KNN; t++) {
        int p = myp[t];
        float4 g = g_sorted[p];
        int id = __float_as_int(g.w);
        float4 ic = g_icov_o[id];
        float ddx = qx - g.x, ddy = qy - g.y, ddz = qz - g.z;
        float e = fmaf(ddx*ddx, ic.x, fmaf(ddy*ddy, ic.y, ddz*ddz*ic.z));
        float wgt = __expf(-0.5f * e);
        wsum += wgt;
        const float4* fp = feats4 + (size_t)id * (NF/4);
#pragma unroll
        for (int cc = 0; cc < NF/4; cc++) {
            float4 fv = fp[cc];
            acc[4*cc+0] = fmaf(wgt, fv.x, acc[4*cc+0]);
            acc[4*cc+1] = fmaf(wgt, fv.y, acc[4*cc+1]);
            acc[4*cc+2] = fmaf(wgt, fv.z, acc[4*cc+2]);
            acc[4*cc+3] = fmaf(wgt, fv.w, acc[4*cc+3]);
        }
    }
    float inv = 1.f / (wsum + 1e-8f);
    float4* o4 = (float4*)(out + (size_t)q * NF);
#pragma unroll
    for (int cc = 0; cc < NF/4; cc++)
        o4[cc] = make_float4(acc[4*cc+0]*inv, acc[4*cc+1]*inv,
                             acc[4*cc+2]*inv, acc[4*cc+3]*inv);
}

// One block (64 threads) per cell; positions-only window in 12.8KB smem.
// Single pass top-16 with slot indices packed into the distance mantissa.
__global__ __launch_bounds__(64, 12)
void splash_cell(const float* __restrict__ coords,
                 const float4* __restrict__ feats4,
                 float* __restrict__ out) {
    __shared__ float4 spos[CAP];

    const int cell = blockIdx.x;
    const int q0 = g_qstart[cell], q1 = g_qstart[cell + 1];
    if (q0 == q1) return;

    const int cx = cell & 7, cy = (cell >> 3) & 7, cz = cell >> 6;
    const int x0 = max(cx - 1, 0), x1e = min(cx + 1, G - 1) + 1;

    int nS = 0;
    bool ovf = false;
    for (int z = max(cz - 1, 0); z <= min(cz + 1, G - 1); ++z) {
        for (int y = max(cy - 1, 0); y <= min(cy + 1, G - 1); ++y) {
            int base = (z * G + y) * G;
            int r0 = g_start[base + x0];
            int r1 = g_start[base + x1e];
            int len = r1 - r0;
            if (ovf || nS + len > CAP) { ovf = true; continue; }
            for (int i = threadIdx.x; i < len; i += blockDim.x)
                spos[nS + i] = g_sorted[r0 + i];
            nS += len;
        }
    }
    __syncthreads();

    const float h = 1.0f / (float)G;

    for (int qi = q0 + threadIdx.x; qi < q1; qi += blockDim.x) {
        const int q = g_qorder[qi];
        const float qx = coords[3*q+0], qy = coords[3*q+1], qz = coords[3*q+2];

        if (ovf) { fallback_query(q, qx, qy, qz, cx, cy, cz, feats4, out); continue; }

        // Pass 1 (only pass): top-16 keys, slot packed into low mantissa bits.
        unsigned key[KNN];
#pragma unroll
        for (int t = 0; t < KNN; t++) key[t] = 0xFFFFFFFFu;

#pragma unroll 4
        for (int j = 0; j < nS; ++j) {
            float4 g = spos[j];
            float ddx = qx - g.x, ddy = qy - g.y, ddz = qz - g.z;
            float d2 = fmaf(ddx, ddx, fmaf(ddy, ddy, ddz * ddz));
            unsigned kn = (__float_as_uint(d2) & ~IDXMASK) | (unsigned)j;
            if (kn < key[0]) {
                key[0] = kn;
#pragma unroll
                for (int t = 0; t < KNN - 1; t++) {
                    unsigned a = umax(key[t], key[t+1]);
                    unsigned b = umin(key[t], key[t+1]);
                    key[t] = a; key[t+1] = b;
                }
            }
        }

        // Exact r=1 termination (clipped faces have nothing beyond them).
        float m = 1e30f;
        if (cx - 1 > 0)     m = fminf(m, qx - (float)(cx - 1) * h);
        if (cx + 1 < G - 1) m = fminf(m, (float)(cx + 2) * h - qx);
        if (cy - 1 > 0)     m = fminf(m, qy - (float)(cy - 1) * h);
        if (cy + 1 < G - 1) m = fminf(m, (float)(cy + 2) * h - qy);
        if (cz - 1 > 0)     m = fminf(m, qz - (float)(cz - 1) * h);
        if (cz + 1 < G - 1) m = fminf(m, (float)(cz + 2) * h - qz);
        float d16 = __uint_as_float(key[0] & ~IDXMASK);
        if (d16 > m * m) {
            fallback_query(q, qx, qy, qz, cx, cy, cz, feats4, out);
            continue;
        }

        // Aggregation: weights recomputed exactly from positions + icov.
        float acc[NF];
#pragma unroll
        for (int f = 0; f < NF; f++) acc[f] = 0.f;
        float wsum = 0.f;
#pragma unroll
        for (int t = 0; t < KNN; t++) {
            int p = (int)(key[t] & IDXMASK);
            float4 g = spos[p];
            int id = __float_as_int(g.w);
            float4 ic = g_icov_o[id];
            float ddx = qx - g.x, ddy = qy - g.y, ddz = qz - g.z;
            float e = fmaf(ddx*ddx, ic.x, fmaf(ddy*ddy, ic.y, ddz*ddz*ic.z));
            float wgt = __expf(-0.5f * e);
            wsum += wgt;
            const float4* fp = feats4 + (size_t)id * (NF/4);
#pragma unroll
            for (int cc = 0; cc < NF/4; cc++) {
                float4 fv = fp[cc];
                acc[4*cc+0] = fmaf(wgt, fv.x, acc[4*cc+0]);
                acc[4*cc+1] = fmaf(wgt, fv.y, acc[4*cc+1]);
                acc[4*cc+2] = fmaf(wgt, fv.z, acc[4*cc+2]);
                acc[4*cc+3] = fmaf(wgt, fv.w, acc[4*cc+3]);
            }
        }
        float inv = 1.f / (wsum + 1e-8f);
        float4* o4 = (float4*)(out + (size_t)q * NF);
#pragma unroll
        for (int cc = 0; cc < NF/4; cc++)
            o4[cc] = make_float4(acc[4*cc+0]*inv, acc[4*cc+1]*inv,
                                 acc[4*cc+2]*inv, acc[4*cc+3]*inv);
    }
}

extern "C" void kernel_launch(void* const* d_in, const int* in_sizes, int n_in,
                              void* d_out, int out_size) {
    const float* coords = (const float*)d_in[0];
    const float* means  = (const float*)d_in[1];
    const float* logc   = (const float*)d_in[2];
    const float* feats  = (const float*)d_in[3];
    float* out = (float*)d_out;

    int M = in_sizes[0] / 3;
    int N = in_sizes[1] / 3;
    int mx = (M > N ? M : N);

    k_clear<<<(NC + 255) / 256, 256>>>();
    k_hist<<<(mx + 255) / 256, 256>>>(means, logc, N, coords, M);
    k_scan<<<1, NC>>>();
    k_scatter<<<(mx + 255) / 256, 256>>>(means, N, M);
    splash_cell<<<NC, 64>>>(coords, (const float4*)feats, out);
}

// round 5
// speedup vs baseline: 1.1192x; 1.1192x over previous
#include <cuda_runtime.h>
#include <math.h>
#include <float.h>

#define G 8
#define NC (G*G*G)
#define MAXN 10016
#define MAXM 32768
#define KNN 16
#define NF 32
#define CAP 800
#define IDXMASK 0x7FFu

// ---- device scratch (allocation-free) ----
__device__ float4 g_sorted[MAXN];   // cell-ordered: (x,y,z, orig-idx bits)
__device__ float4 g_icov_s[MAXN];   // cell-ordered inverse covariances
__device__ int g_cnt[NC], g_start[NC + 1];
__device__ int g_qcnt[NC], g_qstart[NC + 1];
__device__ int g_gcell[MAXN], g_grank[MAXN];
__device__ int g_qcell[MAXM], g_qrank[MAXM];
__device__ int g_qorder[MAXM];

// 27 neighbor offsets in distance-ring order: center, faces, edges, corners.
__device__ __constant__ signed char OX[27] =
    {0,  1,-1, 0, 0, 0, 0,  1, 1,-1,-1, 1, 1,-1,-1, 0, 0, 0, 0,  1, 1, 1, 1,-1,-1,-1,-1};
__device__ __constant__ signed char OY[27] =
    {0,  0, 0, 1,-1, 0, 0,  1,-1, 1,-1, 0, 0, 0, 0, 1, 1,-1,-1,  1, 1,-1,-1, 1, 1,-1,-1};
__device__ __constant__ signed char OZ[27] =
    {0,  0, 0, 0, 0, 1,-1,  0, 0, 0, 0, 1,-1, 1,-1, 1,-1, 1,-1,  1,-1, 1,-1, 1,-1, 1,-1};

__device__ __forceinline__ int cell_coord(float v) {
    int c = (int)(v * (float)G);
    return min(G - 1, max(0, c));
}

__global__ void k_hist(const float* __restrict__ means, int N,
                       const float* __restrict__ coords, int M) {
    int i = blockIdx.x * blockDim.x + threadIdx.x;
    if (i < N) {
        int c = (cell_coord(means[3*i+2]) * G + cell_coord(means[3*i+1])) * G
                + cell_coord(means[3*i+0]);
        g_gcell[i] = c;
        g_grank[i] = atomicAdd(&g_cnt[c], 1);
    }
    if (i < M) {
        int c = (cell_coord(coords[3*i+2]) * G + cell_coord(coords[3*i+1])) * G
                + cell_coord(coords[3*i+0]);
        g_qcell[i] = c;
        g_qrank[i] = atomicAdd(&g_qcnt[c], 1);
    }
}

// Exclusive scans of both histograms; also zeroes counters for the next
// graph replay (replaces a dedicated clear kernel).
__global__ void k_scan() {
    __shared__ int ws[16];
    int t = threadIdx.x, lane = t & 31, w = t >> 5;

    int s = g_cnt[t];
    g_cnt[t] = 0;
    for (int o = 1; o < 32; o <<= 1) {
        int u = __shfl_up_sync(0xffffffffu, s, o);
        if (lane >= o) s += u;
    }
    if (lane == 31) ws[w] = s;
    __syncthreads();
    if (t < 32) {
        int v = (t < 16) ? ws[t] : 0;
        for (int o = 1; o < 16; o <<= 1) {
            int u = __shfl_up_sync(0xffffffffu, v, o);
            if (t >= o) v += u;
        }
        if (t < 16) ws[t] = v;
    }
    __syncthreads();
    g_start[t + 1] = (w ? ws[w - 1] : 0) + s;
    if (t == 0) g_start[0] = 0;
    __syncthreads();

    s = g_qcnt[t];
    g_qcnt[t] = 0;
    for (int o = 1; o < 32; o <<= 1) {
        int u = __shfl_up_sync(0xffffffffu, s, o);
        if (lane >= o) s += u;
    }
    if (lane == 31) ws[w] = s;
    __syncthreads();
    if (t < 32) {
        int v = (t < 16) ? ws[t] : 0;
        for (int o = 1; o < 16; o <<= 1) {
            int u = __shfl_up_sync(0xffffffffu, v, o);
            if (t >= o) v += u;
        }
        if (t < 16) ws[t] = v;
    }
    __syncthreads();
    g_qstart[t + 1] = (w ? ws[w - 1] : 0) + s;
    if (t == 0) g_qstart[0] = 0;
}

__global__ void k_scatter(const float* __restrict__ means,
                          const float* __restrict__ logc, int N, int M) {
    int i = blockIdx.x * blockDim.x + threadIdx.x;
    if (i < N) {
        int pos = g_start[g_gcell[i]] + g_grank[i];
        g_sorted[pos] = make_float4(means[3*i], means[3*i+1], means[3*i+2],
                                    __int_as_float(i));
        g_icov_s[pos] = make_float4(expf(-logc[3*i]), expf(-logc[3*i+1]),
                                    expf(-logc[3*i+2]), 0.f);
    }
    if (i < M) {
        int pos = g_qstart[g_qcell[i]] + g_qrank[i];
        g_qorder[pos] = i;
    }
}

// Exact per-query fallback (rare): gmem ring expansion + threshold rescan.
__device__ __noinline__ void fallback_query(int q, float qx, float qy, float qz,
                                            int cx, int cy, int cz,
                                            const float4* __restrict__ feats4,
                                            float* __restrict__ out) {
    const float h = 1.0f / (float)G;
    float bd[KNN];
#pragma unroll
    for (int t = 0; t < KNN; t++) bd[t] = FLT_MAX;

    int rfin = 1;
    for (int r = 1; r <= G; ++r) {
        rfin = r;
        for (int dz = -r; dz <= r; ++dz) {
            int z = cz + dz; if ((unsigned)z >= G) continue;
            for (int dy = -r; dy <= r; ++dy) {
                int y = cy + dy; if ((unsigned)y >= G) continue;
                bool edge = (dz == -r) | (dz == r) | (dy == -r) | (dy == r);
                int step = (r > 1 && !edge) ? 2 * r : 1;
                for (int dx = -r; dx <= r; dx += step) {
                    int x = cx + dx; if ((unsigned)x >= G) continue;
                    int cid = (z * G + y) * G + x;
                    int c0 = g_start[cid], c1 = g_start[cid + 1];
                    for (int c = c0; c < c1; ++c) {
                        float4 g = g_sorted[c];
                        float ddx = qx - g.x, ddy = qy - g.y, ddz = qz - g.z;
                        float d2 = fmaf(ddx, ddx, fmaf(ddy, ddy, ddz * ddz));
                        if (d2 < bd[0]) {
                            bd[0] = d2;
#pragma unroll
                            for (int t = 0; t < KNN - 1; t++) {
                                float a = fmaxf(bd[t], bd[t+1]);
                                float b = fminf(bd[t], bd[t+1]);
                                bd[t] = a; bd[t+1] = b;
                            }
                        }
                    }
                }
            }
        }
        float m = 1e30f;
        if (cx - r > 0)     m = fminf(m, qx - (float)(cx - r) * h);
        if (cx + r < G - 1) m = fminf(m, (float)(cx + r + 1) * h - qx);
        if (cy - r > 0)     m = fminf(m, qy - (float)(cy - r) * h);
        if (cy + r < G - 1) m = fminf(m, (float)(cy + r + 1) * h - qy);
        if (cz - r > 0)     m = fminf(m, qz - (float)(cz - r) * h);
        if (cz + r < G - 1) m = fminf(m, (float)(cz + r + 1) * h - qz);
        if (bd[0] <= m * m) break;
    }
    const float T = bd[0];

    int myp[KNN];
#pragma unroll
    for (int t = 0; t < KNN; t++) myp[t] = 0;
    int cnt = 0;
    {
        const int r = rfin;
        for (int dz = -r; dz <= r; ++dz) {
            int z = cz + dz; if ((unsigned)z >= G) continue;
            for (int dy = -r; dy <= r; ++dy) {
                int y = cy + dy; if ((unsigned)y >= G) continue;
                for (int dx = -r; dx <= r; ++dx) {
                    int x = cx + dx; if ((unsigned)x >= G) continue;
                    int cid = (z * G + y) * G + x;
                    int c0 = g_start[cid], c1 = g_start[cid + 1];
                    for (int c = c0; c < c1; ++c) {
                        float4 g = g_sorted[c];
                        float ddx = qx - g.x, ddy = qy - g.y, ddz = qz - g.z;
                        float d2 = fmaf(ddx, ddx, fmaf(ddy, ddy, ddz * ddz));
                        if (d2 <= T && cnt < KNN) { myp[cnt] = c; cnt++; }
                    }
                }
            }
        }
    }

    float acc[NF];
#pragma unroll
    for (int f = 0; f < NF; f++) acc[f] = 0.f;
    float wsum = 0.f;
#pragma unroll
    for (int t = 0; t < KNN; t++) {
        int p = myp[t];
        float4 g = g_sorted[p];
        float4 ic = g_icov_s[p];
        int id = __float_as_int(g.w);
        float ddx = qx - g.x, ddy = qy - g.y, ddz = qz - g.z;
        float e = fmaf(ddx*ddx, ic.x, fmaf(ddy*ddy, ic.y, ddz*ddz*ic.z));
        float wgt = __expf(-0.5f * e);
        wsum += wgt;
        const float4* fp = feats4 + (size_t)id * (NF/4);
#pragma unroll
        for (int cc = 0; cc < NF/4; cc++) {
            float4 fv = fp[cc];
            acc[4*cc+0] = fmaf(wgt, fv.x, acc[4*cc+0]);
            acc[4*cc+1] = fmaf(wgt, fv.y, acc[4*cc+1]);
            acc[4*cc+2] = fmaf(wgt, fv.z, acc[4*cc+2]);
            acc[4*cc+3] = fmaf(wgt, fv.w, acc[4*cc+3]);
        }
    }
    float inv = 1.f / (wsum + 1e-8f);
    float4* o4 = (float4*)(out + (size_t)q * NF);
#pragma unroll
    for (int cc = 0; cc < NF/4; cc++)
        o4[cc] = make_float4(acc[4*cc+0]*inv, acc[4*cc+1]*inv,
                             acc[4*cc+2]*inv, acc[4*cc+3]*inv);
}

// One block (128 threads) per cell, TWO threads per query.
// Window copied in distance-ring order (quasi-sorted stream -> few inserts).
__global__ __launch_bounds__(128)
void splash_cell(const float* __restrict__ coords,
                 const float4* __restrict__ feats4,
                 float* __restrict__ out) {
    __shared__ float4 spos[CAP];
    __shared__ float4 sicv[CAP];

    const int cell = blockIdx.x;
    const int q0 = g_qstart[cell], q1 = g_qstart[cell + 1];
    if (q0 == q1) return;

    const int cx = cell & 7, cy = (cell >> 3) & 7, cz = cell >> 6;

    // Ring-ordered cooperative window copy.
    int nS = 0;
    bool ovf = false;
    for (int c = 0; c < 27; ++c) {
        int x = cx + OX[c], y = cy + OY[c], z = cz + OZ[c];
        if ((unsigned)x >= G || (unsigned)y >= G || (unsigned)z >= G) continue;
        int cid = (z * G + y) * G + x;
        int r0 = g_start[cid];
        int len = g_start[cid + 1] - r0;
        if (ovf || nS + len > CAP) { ovf = true; continue; }
        for (int i = threadIdx.x; i < len; i += 128) {
            spos[nS + i] = g_sorted[r0 + i];
            sicv[nS + i] = g_icov_s[r0 + i];
        }
        nS += len;
    }
    __syncthreads();

    const float h = 1.0f / (float)G;
    const int r = threadIdx.x & 1;          // role within the pair
    const int pair = threadIdx.x >> 1;      // 64 pairs per block

    for (int qi = q0 + pair; qi < q1; qi += 64) {
        const int q = g_qorder[qi];
        const float qx = coords[3*q+0], qy = coords[3*q+1], qz = coords[3*q+2];

        if (ovf || nS < KNN) {
            if (r == 0) fallback_query(q, qx, qy, qz, cx, cy, cz, feats4, out);
            continue;
        }

        // Interleaved half-stream scan: thread r takes j = r, r+2, r+4, ...
        unsigned key[KNN];
#pragma unroll
        for (int t = 0; t < KNN; t++) key[t] = 0xFFFFFFFFu;

#pragma unroll 2
        for (int j = r; j < nS; j += 2) {
            float4 g = spos[j];
            float ddx = qx - g.x, ddy = qy - g.y, ddz = qz - g.z;
            float d2 = fmaf(ddx, ddx, fmaf(ddy, ddy, ddz * ddz));
            unsigned kn = (__float_as_uint(d2) & ~IDXMASK) | (unsigned)j;
            if (kn < key[0]) {
                key[0] = kn;
#pragma unroll
                for (int t = 0; t < KNN - 1; t++) {
                    unsigned a = umax(key[t], key[t+1]);
                    unsigned b = umin(key[t], key[t+1]);
                    key[t] = a; key[t+1] = b;
                }
            }
        }

        // Pair merge (bitonic top-k): c[t] = min(mine[t], partner[15-t]).
        // Partner's c is exactly my reverse, so each thread's c[0..7]
        // partitions the 16-set between the two threads.
        unsigned amask = __activemask();
        unsigned c[KNN];
#pragma unroll
        for (int t = 0; t < KNN; t++) {
            unsigned pk = __shfl_xor_sync(amask, key[KNN - 1 - t], 1);
            c[t] = umin(key[t], pk);
        }
        unsigned mx = c[0];
#pragma unroll
        for (int t = 1; t < KNN; t++) mx = umax(mx, c[t]);

        // Exact r=1 termination (clipped faces have nothing beyond them).
        float m = 1e30f;
        if (cx - 1 > 0)     m = fminf(m, qx - (float)(cx - 1) * h);
        if (cx + 1 < G - 1) m = fminf(m, (float)(cx + 2) * h - qx);
        if (cy - 1 > 0)     m = fminf(m, qy - (float)(cy - 1) * h);
        if (cy + 1 < G - 1) m = fminf(m, (float)(cy + 2) * h - qy);
        if (cz - 1 > 0)     m = fminf(m, qz - (float)(cz - 1) * h);
        if (cz + 1 < G - 1) m = fminf(m, (float)(cz + 2) * h - qz);
        float d16 = __uint_as_float(mx & ~IDXMASK);
        if (d16 > m * m) {
            if (r == 0) fallback_query(q, qx, qy, qz, cx, cy, cz, feats4, out);
            continue;
        }

        // Split aggregation: each thread handles its own c[0..7].
        float acc[NF];
#pragma unroll
        for (int f = 0; f < NF; f++) acc[f] = 0.f;
        float wsum = 0.f;
#pragma unroll
        for (int t = 0; t < KNN/2; t++) {
            int p = (int)(c[t] & IDXMASK);
            float4 g = spos[p];
            float4 ic = sicv[p];
            int id = __float_as_int(g.w);
            float ddx = qx - g.x, ddy = qy - g.y, ddz = qz - g.z;
            float e = fmaf(ddx*ddx, ic.x, fmaf(ddy*ddy, ic.y, ddz*ddz*ic.z));
            float wgt = __expf(-0.5f * e);
            wsum += wgt;
            const float4* fp = feats4 + (size_t)id * (NF/4);
#pragma unroll
            for (int cc = 0; cc < NF/4; cc++) {
                float4 fv = fp[cc];
                acc[4*cc+0] = fmaf(wgt, fv.x, acc[4*cc+0]);
                acc[4*cc+1] = fmaf(wgt, fv.y, acc[4*cc+1]);
                acc[4*cc+2] = fmaf(wgt, fv.z, acc[4*cc+2]);
                acc[4*cc+3] = fmaf(wgt, fv.w, acc[4*cc+3]);
            }
        }
        // Pair butterfly reduce.
        wsum += __shfl_xor_sync(amask, wsum, 1);
#pragma unroll
        for (int f = 0; f < NF; f++)
            acc[f] += __shfl_xor_sync(amask, acc[f], 1);

        float inv = 1.f / (wsum + 1e-8f);
        // Each thread writes half the output (4 float4s).
        float4* o4 = (float4*)(out + (size_t)q * NF);
#pragma unroll
        for (int cc = 0; cc < NF/8; cc++) {
            int b = r * (NF/8) + cc;
            o4[b] = make_float4(acc[4*b+0]*inv, acc[4*b+1]*inv,
                                acc[4*b+2]*inv, acc[4*b+3]*inv);
        }
    }
}

extern "C" void kernel_launch(void* const* d_in, const int* in_sizes, int n_in,
                              void* d_out, int out_size) {
    const float* coords = (const float*)d_in[0];
    const float* means  = (const float*)d_in[1];
    const float* logc   = (const float*)d_in[2];
    const float* feats  = (const float*)d_in[3];
    float* out = (float*)d_out;

    int M = in_sizes[0] / 3;
    int N = in_sizes[1] / 3;
    int mx = (M > N ? M : N);

    k_hist<<<(mx + 255) / 256, 256>>>(means, N, coords, M);
    k_scan<<<1, NC>>>();
    k_scatter<<<(mx + 255) / 256, 256>>>(means, logc, N, M);
    splash_cell<<<NC, 128>>>(coords, (const float4*)feats, out);
}

// round 6
// speedup vs baseline: 1.1201x; 1.0008x over previous
#include <cuda_runtime.h>
#include <math.h>
#include <float.h>

#define G 8
#define NC (G*G*G)
#define MAXN 10016
#define MAXM 32768
#define KNN 16
#define NF 32
#define CAP 800
#define IDXMASK 0x7FFu
#define QCHUNK 64           // queries per block-chunk
#define SPLITS 2            // blocks per cell

// ---- device scratch (allocation-free) ----
__device__ float4 g_sorted[MAXN];   // cell-ordered: (x,y,z, orig-idx bits)
__device__ float4 g_icov_s[MAXN];   // cell-ordered inverse covariances
__device__ int g_cnt[NC], g_start[NC + 1];
__device__ int g_qcnt[NC], g_qstart[NC + 1];
__device__ int g_gcell[MAXN], g_grank[MAXN];
__device__ int g_qcell[MAXM], g_qrank[MAXM];
__device__ int g_qorder[MAXM];

// 27 neighbor offsets in distance-ring order: center, faces, edges, corners.
__device__ __constant__ signed char OX[27] =
    {0,  1,-1, 0, 0, 0, 0,  1, 1,-1,-1, 1, 1,-1,-1, 0, 0, 0, 0,  1, 1, 1, 1,-1,-1,-1,-1};
__device__ __constant__ signed char OY[27] =
    {0,  0, 0, 1,-1, 0, 0,  1,-1, 1,-1, 0, 0, 0, 0, 1, 1,-1,-1,  1, 1,-1,-1, 1, 1,-1,-1};
__device__ __constant__ signed char OZ[27] =
    {0,  0, 0, 0, 0, 1,-1,  0, 0, 0, 0, 1,-1, 1,-1, 1,-1, 1,-1,  1,-1, 1,-1, 1,-1, 1,-1};

__device__ __forceinline__ int cell_coord(float v) {
    int c = (int)(v * (float)G);
    return min(G - 1, max(0, c));
}

__global__ void k_hist(const float* __restrict__ means, int N,
                       const float* __restrict__ coords, int M) {
    int i = blockIdx.x * blockDim.x + threadIdx.x;
    if (i < N) {
        int c = (cell_coord(means[3*i+2]) * G + cell_coord(means[3*i+1])) * G
                + cell_coord(means[3*i+0]);
        g_gcell[i] = c;
        g_grank[i] = atomicAdd(&g_cnt[c], 1);
    }
    if (i < M) {
        int c = (cell_coord(coords[3*i+2]) * G + cell_coord(coords[3*i+1])) * G
                + cell_coord(coords[3*i+0]);
        g_qcell[i] = c;
        g_qrank[i] = atomicAdd(&g_qcnt[c], 1);
    }
}

// Exclusive scans of both histograms; zeroes counters for the next replay.
__global__ void k_scan() {
    __shared__ int ws[16];
    int t = threadIdx.x, lane = t & 31, w = t >> 5;

    int s = g_cnt[t];
    g_cnt[t] = 0;
    for (int o = 1; o < 32; o <<= 1) {
        int u = __shfl_up_sync(0xffffffffu, s, o);
        if (lane >= o) s += u;
    }
    if (lane == 31) ws[w] = s;
    __syncthreads();
    if (t < 32) {
        int v = (t < 16) ? ws[t] : 0;
        for (int o = 1; o < 16; o <<= 1) {
            int u = __shfl_up_sync(0xffffffffu, v, o);
            if (t >= o) v += u;
        }
        if (t < 16) ws[t] = v;
    }
    __syncthreads();
    g_start[t + 1] = (w ? ws[w - 1] : 0) + s;
    if (t == 0) g_start[0] = 0;
    __syncthreads();

    s = g_qcnt[t];
    g_qcnt[t] = 0;
    for (int o = 1; o < 32; o <<= 1) {
        int u = __shfl_up_sync(0xffffffffu, s, o);
        if (lane >= o) s += u;
    }
    if (lane == 31) ws[w] = s;
    __syncthreads();
    if (t < 32) {
        int v = (t < 16) ? ws[t] : 0;
        for (int o = 1; o < 16; o <<= 1) {
            int u = __shfl_up_sync(0xffffffffu, v, o);
            if (t >= o) v += u;
        }
        if (t < 16) ws[t] = v;
    }
    __syncthreads();
    g_qstart[t + 1] = (w ? ws[w - 1] : 0) + s;
    if (t == 0) g_qstart[0] = 0;
}

__global__ void k_scatter(const float* __restrict__ means,
                          const float* __restrict__ logc, int N, int M) {
    int i = blockIdx.x * blockDim.x + threadIdx.x;
    if (i < N) {
        int pos = g_start[g_gcell[i]] + g_grank[i];
        g_sorted[pos] = make_float4(means[3*i], means[3*i+1], means[3*i+2],
                                    __int_as_float(i));
        g_icov_s[pos] = make_float4(expf(-logc[3*i]), expf(-logc[3*i+1]),
                                    expf(-logc[3*i+2]), 0.f);
    }
    if (i < M) {
        int pos = g_qstart[g_qcell[i]] + g_qrank[i];
        g_qorder[pos] = i;
    }
}

// Exact per-query fallback (rare): gmem ring expansion + threshold rescan.
__device__ __noinline__ void fallback_query(int q, float qx, float qy, float qz,
                                            int cx, int cy, int cz,
                                            const float4* __restrict__ feats4,
                                            float* __restrict__ out) {
    const float h = 1.0f / (float)G;
    float bd[KNN];
#pragma unroll
    for (int t = 0; t < KNN; t++) bd[t] = FLT_MAX;

    int rfin = 1;
    for (int r = 1; r <= G; ++r) {
        rfin = r;
        for (int dz = -r; dz <= r; ++dz) {
            int z = cz + dz; if ((unsigned)z >= G) continue;
            for (int dy = -r; dy <= r; ++dy) {
                int y = cy + dy; if ((unsigned)y >= G) continue;
                bool edge = (dz == -r) | (dz == r) | (dy == -r) | (dy == r);
                int step = (r > 1 && !edge) ? 2 * r : 1;
                for (int dx = -r; dx <= r; dx += step) {
                    int x = cx + dx; if ((unsigned)x >= G) continue;
                    int cid = (z * G + y) * G + x;
                    int c0 = g_start[cid], c1 = g_start[cid + 1];
                    for (int c = c0; c < c1; ++c) {
                        float4 g = g_sorted[c];
                        float ddx = qx - g.x, ddy = qy - g.y, ddz = qz - g.z;
                        float d2 = fmaf(ddx, ddx, fmaf(ddy, ddy, ddz * ddz));
                        if (d2 < bd[0]) {
                            bd[0] = d2;
#pragma unroll
                            for (int t = 0; t < KNN - 1; t++) {
                                float a = fmaxf(bd[t], bd[t+1]);
                                float b = fminf(bd[t], bd[t+1]);
                                bd[t] = a; bd[t+1] = b;
                            }
                        }
                    }
                }
            }
        }
        float m = 1e30f;
        if (cx - r > 0)     m = fminf(m, qx - (float)(cx - r) * h);
        if (cx + r < G - 1) m = fminf(m, (float)(cx + r + 1) * h - qx);
        if (cy - r > 0)     m = fminf(m, qy - (float)(cy - r) * h);
        if (cy + r < G - 1) m = fminf(m, (float)(cy + r + 1) * h - qy);
        if (cz - r > 0)     m = fminf(m, qz - (float)(cz - r) * h);
        if (cz + r < G - 1) m = fminf(m, (float)(cz + r + 1) * h - qz);
        if (bd[0] <= m * m) break;
    }
    const float T = bd[0];

    int myp[KNN];
#pragma unroll
    for (int t = 0; t < KNN; t++) myp[t] = 0;
    int cnt = 0;
    {
        const int r = rfin;
        for (int dz = -r; dz <= r; ++dz) {
            int z = cz + dz; if ((unsigned)z >= G) continue;
            for (int dy = -r; dy <= r; ++dy) {
                int y = cy + dy; if ((unsigned)y >= G) continue;
                for (int dx = -r; dx <= r; ++dx) {
                    int x = cx + dx; if ((unsigned)x >= G) continue;
                    int cid = (z * G + y) * G + x;
                    int c0 = g_start[cid], c1 = g_start[cid + 1];
                    for (int c = c0; c < c1; ++c) {
                        float4 g = g_sorted[c];
                        float ddx = qx - g.x, ddy = qy - g.y, ddz = qz - g.z;
                        float d2 = fmaf(ddx, ddx, fmaf(ddy, ddy, ddz * ddz));
                        if (d2 <= T && cnt < KNN) { myp[cnt] = c; cnt++; }
                    }
                }
            }
        }
    }

    float acc[NF];
#pragma unroll
    for (int f = 0; f < NF; f++) acc[f] = 0.f;
    float wsum = 0.f;
#pragma unroll
    for (int t = 0; t < KNN; t++) {
        int p = myp[t];
        float4 g = g_sorted[p];
        float4 ic = g_icov_s[p];
        int id = __float_as_int(g.w);
        float ddx = qx - g.x, ddy = qy - g.y, ddz = qz - g.z;
        float e = fmaf(ddx*ddx, ic.x, fmaf(ddy*ddy, ic.y, ddz*ddz*ic.z));
        float wgt = __expf(-0.5f * e);
        wsum += wgt;
        const float4* fp = feats4 + (size_t)id * (NF/4);
#pragma unroll
        for (int cc = 0; cc < NF/4; cc++) {
            float4 fv = fp[cc];
            acc[4*cc+0] = fmaf(wgt, fv.x, acc[4*cc+0]);
            acc[4*cc+1] = fmaf(wgt, fv.y, acc[4*cc+1]);
            acc[4*cc+2] = fmaf(wgt, fv.z, acc[4*cc+2]);
            acc[4*cc+3] = fmaf(wgt, fv.w, acc[4*cc+3]);
        }
    }
    float inv = 1.f / (wsum + 1e-8f);
    float4* o4 = (float4*)(out + (size_t)q * NF);
#pragma unroll
    for (int cc = 0; cc < NF/4; cc++)
        o4[cc] = make_float4(acc[4*cc+0]*inv, acc[4*cc+1]*inv,
                             acc[4*cc+2]*inv, acc[4*cc+3]*inv);
}

// SPLITS blocks per cell, 128 threads, two threads per query.
// Block h handles query chunk starting at q0 + h*QCHUNK, striding
// SPLITS*QCHUNK. Ring-ordered window in smem.
__global__ __launch_bounds__(128, 8)
void splash_cell(const float* __restrict__ coords,
                 const float4* __restrict__ feats4,
                 float* __restrict__ out) {
    __shared__ float4 spos[CAP];
    __shared__ float4 sicv[CAP];

    const int cell = blockIdx.x >> 1;
    const int half = blockIdx.x & 1;
    const int q0 = g_qstart[cell], q1 = g_qstart[cell + 1];
    const int qbeg = q0 + half * QCHUNK;
    if (qbeg >= q1) return;

    const int cx = cell & 7, cy = (cell >> 3) & 7, cz = cell >> 6;

    // Ring-ordered cooperative window copy.
    int nS = 0;
    bool ovf = false;
    for (int c = 0; c < 27; ++c) {
        int x = cx + OX[c], y = cy + OY[c], z = cz + OZ[c];
        if ((unsigned)x >= G || (unsigned)y >= G || (unsigned)z >= G) continue;
        int cid = (z * G + y) * G + x;
        int r0 = g_start[cid];
        int len = g_start[cid + 1] - r0;
        if (ovf || nS + len > CAP) { ovf = true; continue; }
        for (int i = threadIdx.x; i < len; i += 128) {
            spos[nS + i] = g_sorted[r0 + i];
            sicv[nS + i] = g_icov_s[r0 + i];
        }
        nS += len;
    }
    __syncthreads();

    const float h = 1.0f / (float)G;
    const int r = threadIdx.x & 1;
    const int pair = threadIdx.x >> 1;

    for (int qi = qbeg + pair; qi < q1; qi += SPLITS * QCHUNK) {
        const int q = g_qorder[qi];
        const float qx = coords[3*q+0], qy = coords[3*q+1], qz = coords[3*q+2];

        if (ovf || nS < KNN) {
            if (r == 0) fallback_query(q, qx, qy, qz, cx, cy, cz, feats4, out);
            continue;
        }

        // Interleaved half-stream scan: thread r takes j = r, r+2, ...
        unsigned key[KNN];
#pragma unroll
        for (int t = 0; t < KNN; t++) key[t] = 0xFFFFFFFFu;

#pragma unroll 4
        for (int j = r; j < nS; j += 2) {
            float4 g = spos[j];
            float ddx = qx - g.x, ddy = qy - g.y, ddz = qz - g.z;
            float d2 = fmaf(ddx, ddx, fmaf(ddy, ddy, ddz * ddz));
            unsigned kn = (__float_as_uint(d2) & ~IDXMASK) | (unsigned)j;
            if (kn < key[0]) {
                key[0] = kn;
#pragma unroll
                for (int t = 0; t < KNN - 1; t++) {
                    unsigned a = umax(key[t], key[t+1]);
                    unsigned b = umin(key[t], key[t+1]);
                    key[t] = a; key[t+1] = b;
                }
            }
        }

        // Pair merge (bitonic top-k): c[t] = min(mine[t], partner[15-t]).
        unsigned amask = __activemask();
        unsigned c[KNN];
#pragma unroll
        for (int t = 0; t < KNN; t++) {
            unsigned pk = __shfl_xor_sync(amask, key[KNN - 1 - t], 1);
            c[t] = umin(key[t], pk);
        }
        unsigned mx = c[0];
#pragma unroll
        for (int t = 1; t < KNN; t++) mx = umax(mx, c[t]);

        // Exact r=1 termination (clipped faces have nothing beyond them).
        float m = 1e30f;
        if (cx - 1 > 0)     m = fminf(m, qx - (float)(cx - 1) * h);
        if (cx + 1 < G - 1) m = fminf(m, (float)(cx + 2) * h - qx);
        if (cy - 1 > 0)     m = fminf(m, qy - (float)(cy - 1) * h);
        if (cy + 1 < G - 1) m = fminf(m, (float)(cy + 2) * h - qy);
        if (cz - 1 > 0)     m = fminf(m, qz - (float)(cz - 1) * h);
        if (cz + 1 < G - 1) m = fminf(m, (float)(cz + 2) * h - qz);
        float d16 = __uint_as_float(mx & ~IDXMASK);
        if (d16 > m * m) {
            if (r == 0) fallback_query(q, qx, qy, qz, cx, cy, cz, feats4, out);
            continue;
        }

        // Split aggregation: each thread handles its own c[0..7].
        float acc[NF];
#pragma unroll
        for (int f = 0; f < NF; f++) acc[f] = 0.f;
        float wsum = 0.f;
#pragma unroll
        for (int t = 0; t < KNN/2; t++) {
            int p = (int)(c[t] & IDXMASK);
            float4 g = spos[p];
            float4 ic = sicv[p];
            int id = __float_as_int(g.w);
            float ddx = qx - g.x, ddy = qy - g.y, ddz = qz - g.z;
            float e = fmaf(ddx*ddx, ic.x, fmaf(ddy*ddy, ic.y, ddz*ddz*ic.z));
            float wgt = __expf(-0.5f * e);
            wsum += wgt;
            const float4* fp = feats4 + (size_t)id * (NF/4);
#pragma unroll
            for (int cc = 0; cc < NF/4; cc++) {
                float4 fv = fp[cc];
                acc[4*cc+0] = fmaf(wgt, fv.x, acc[4*cc+0]);
                acc[4*cc+1] = fmaf(wgt, fv.y, acc[4*cc+1]);
                acc[4*cc+2] = fmaf(wgt, fv.z, acc[4*cc+2]);
                acc[4*cc+3] = fmaf(wgt, fv.w, acc[4*cc+3]);
            }
        }
        wsum += __shfl_xor_sync(amask, wsum, 1);
#pragma unroll
        for (int f = 0; f < NF; f++)
            acc[f] += __shfl_xor_sync(amask, acc[f], 1);

        float inv = 1.f / (wsum + 1e-8f);
        float4* o4 = (float4*)(out + (size_t)q * NF);
#pragma unroll
        for (int cc = 0; cc < NF/8; cc++) {
            int b = r * (NF/8) + cc;
            o4[b] = make_float4(acc[4*b+0]*inv, acc[4*b+1]*inv,
                                acc[4*b+2]*inv, acc[4*b+3]*inv);
        }
    }
}

extern "C" void kernel_launch(void* const* d_in, const int* in_sizes, int n_in,
                              void* d_out, int out_size) {
    const float* coords = (const float*)d_in[0];
    const float* means  = (const float*)d_in[1];
    const float* logc   = (const float*)d_in[2];
    const float* feats  = (const float*)d_in[3];
    float* out = (float*)d_out;

    int M = in_sizes[0] / 3;
    int N = in_sizes[1] / 3;
    int mx = (M > N ? M : N);

    k_hist<<<(mx + 255) / 256, 256>>>(means, N, coords, M);
    k_scan<<<1, NC>>>();
    k_scatter<<<(mx + 255) / 256, 256>>>(means, logc, N, M);
    splash_cell<<<NC * SPLITS, 128>>>(coords, (const float4*)feats, out);
}

// round 7
// speedup vs baseline: 1.4417x; 1.2871x over previous
#include <cuda_runtime.h>
#include <math.h>
#include <float.h>

#define G 8
#define NC (G*G*G)
#define MAXN 10016
#define MAXM 32768
#define KNN 16
#define NF 32
#define CAPW 512            // per-cell radially-sorted window size
#define WMAX 1024           // gather staging max
#define NBKT 32
#define IDXMASK 0x1FFu      // 9 bits: slot in [0,512)
#define QCHUNK 64
#define SPLITS 2
#define CDMAX 0.1055f       // max center-dist^2 = 3*(1.5/8)^2
#define BWIDTH (CDMAX / (float)NBKT)
#define INVBW ((float)NBKT / CDMAX)

// ---- device scratch (allocation-free) ----
__device__ float4 g_sorted[MAXN];      // cell-ordered: (x,y,z, orig-idx bits)
__device__ float4 g_icov_s[MAXN];      // cell-ordered inverse covariances
__device__ int g_cnt[NC], g_start[NC + 1];
__device__ int g_qcnt[NC], g_qstart[NC + 1];
__device__ int g_gcell[MAXN], g_grank[MAXN];
__device__ int g_qcell[MAXM], g_qrank[MAXM];
__device__ int g_qorder[MAXM];
// per-cell radially sorted windows
__device__ float4 g_winpos[NC * CAPW]; // (x,y,z, |m|^2+3)
__device__ float4 g_winic[NC * CAPW];  // (icx,icy,icz, orig-id bits)
__device__ float  g_wincd[NC * CAPW];  // center-dist^2 (bucket-monotone)
__device__ float  g_wmargin[NC];       // cd^2 below which window is complete
__device__ int    g_nsw[NC];

__device__ __forceinline__ int cell_coord(float v) {
    int c = (int)(v * (float)G);
    return min(G - 1, max(0, c));
}

__global__ void k_hist(const float* __restrict__ means, int N,
                       const float* __restrict__ coords, int M) {
    int i = blockIdx.x * blockDim.x + threadIdx.x;
    if (i < N) {
        int c = (cell_coord(means[3*i+2]) * G + cell_coord(means[3*i+1])) * G
                + cell_coord(means[3*i+0]);
        g_gcell[i] = c;
        g_grank[i] = atomicAdd(&g_cnt[c], 1);
    }
    if (i < M) {
        int c = (cell_coord(coords[3*i+2]) * G + cell_coord(coords[3*i+1])) * G
                + cell_coord(coords[3*i+0]);
        g_qcell[i] = c;
        g_qrank[i] = atomicAdd(&g_qcnt[c], 1);
    }
}

// Exclusive scans of both histograms; zeroes counters for the next replay.
__global__ void k_scan() {
    __shared__ int ws[16];
    int t = threadIdx.x, lane = t & 31, w = t >> 5;

    int s = g_cnt[t];
    g_cnt[t] = 0;
    for (int o = 1; o < 32; o <<= 1) {
        int u = __shfl_up_sync(0xffffffffu, s, o);
        if (lane >= o) s += u;
    }
    if (lane == 31) ws[w] = s;
    __syncthreads();
    if (t < 32) {
        int v = (t < 16) ? ws[t] : 0;
        for (int o = 1; o < 16; o <<= 1) {
            int u = __shfl_up_sync(0xffffffffu, v, o);
            if (t >= o) v += u;
        }
        if (t < 16) ws[t] = v;
    }
    __syncthreads();
    g_start[t + 1] = (w ? ws[w - 1] : 0) + s;
    if (t == 0) g_start[0] = 0;
    __syncthreads();

    s = g_qcnt[t];
    g_qcnt[t] = 0;
    for (int o = 1; o < 32; o <<= 1) {
        int u = __shfl_up_sync(0xffffffffu, s, o);
        if (lane >= o) s += u;
    }
    if (lane == 31) ws[w] = s;
    __syncthreads();
    if (t < 32) {
        int v = (t < 16) ? ws[t] : 0;
        for (int o = 1; o < 16; o <<= 1) {
            int u = __shfl_up_sync(0xffffffffu, v, o);
            if (t >= o) v += u;
        }
        if (t < 16) ws[t] = v;
    }
    __syncthreads();
    g_qstart[t + 1] = (w ? ws[w - 1] : 0) + s;
    if (t == 0) g_qstart[0] = 0;
}

__global__ void k_scatter(const float* __restrict__ means,
                          const float* __restrict__ logc, int N, int M) {
    int i = blockIdx.x * blockDim.x + threadIdx.x;
    if (i < N) {
        int pos = g_start[g_gcell[i]] + g_grank[i];
        g_sorted[pos] = make_float4(means[3*i], means[3*i+1], means[3*i+2],
                                    __int_as_float(i));
        g_icov_s[pos] = make_float4(expf(-logc[3*i]), expf(-logc[3*i+1]),
                                    expf(-logc[3*i+2]), 0.f);
    }
    if (i < M) {
        int pos = g_qstart[g_qcell[i]] + g_qrank[i];
        g_qorder[pos] = i;
    }
}

// Build per-cell radially-ordered windows: gather 27-neighborhood, bucket
// counting-sort by distance^2 from cell center, keep nearest CAPW.
__global__ __launch_bounds__(128)
void k_window() {
    __shared__ float skey[WMAX];
    __shared__ int   sgid[WMAX];
    __shared__ int   cnt[NBKT], st[NBKT + 1], fil[NBKT];

    const int cell = blockIdx.x, tid = threadIdx.x;
    const int cx = cell & 7, cy = (cell >> 3) & 7, cz = cell >> 6;
    const float ccx = (cx + 0.5f) * 0.125f;
    const float ccy = (cy + 0.5f) * 0.125f;
    const float ccz = (cz + 0.5f) * 0.125f;

    if (tid < NBKT) { cnt[tid] = 0; fil[tid] = 0; }
    __syncthreads();

    const int x0 = max(cx - 1, 0), x1e = min(cx + 1, G - 1) + 1;
    int n = 0;
    bool ovf = false;
    for (int z = max(cz - 1, 0); z <= min(cz + 1, G - 1); ++z) {
        for (int y = max(cy - 1, 0); y <= min(cy + 1, G - 1); ++y) {
            int base = (z * G + y) * G;
            int r0 = g_start[base + x0];
            int len = g_start[base + x1e] - r0;
            if (ovf || n + len > WMAX) { ovf = true; continue; }
            for (int i = tid; i < len; i += 128) {
                float4 g = g_sorted[r0 + i];
                float dx = g.x - ccx, dy = g.y - ccy, dz = g.z - ccz;
                float cd = fmaf(dx, dx, fmaf(dy, dy, dz * dz));
                skey[n + i] = cd;
                sgid[n + i] = r0 + i;
                atomicAdd(&cnt[min(NBKT - 1, (int)(cd * INVBW))], 1);
            }
            n += len;
        }
    }
    __syncthreads();

    if (tid < 32) {
        int v = cnt[tid];
        for (int o = 1; o < 32; o <<= 1) {
            int u = __shfl_up_sync(0xffffffffu, v, o);
            if (tid >= o) v += u;
        }
        st[tid + 1] = v;
        if (tid == 0) st[0] = 0;
    }
    __syncthreads();

    if (tid == 0) {
        int nsw = min(n, CAPW);
        float marg = 1e30f;
        if (ovf) { marg = -1.f; nsw = 0; }
        else if (n > CAPW) {
            int t = 0;
            while (t < NBKT && st[t + 1] <= CAPW) t++;
            marg = (float)t * BWIDTH;   // all cd^2 < marg fully retained
        }
        g_wmargin[cell] = marg;
        g_nsw[cell] = nsw;
    }
    __syncthreads();

    if (!ovf) {
        for (int i = tid; i < n; i += 128) {
            float cd = skey[i];
            int b = min(NBKT - 1, (int)(cd * INVBW));
            int pos = st[b] + atomicAdd(&fil[b], 1);
            if (pos < CAPW) {
                int gi = sgid[i];
                float4 gp = g_sorted[gi];
                float m2 = fmaf(gp.x, gp.x, fmaf(gp.y, gp.y, gp.z * gp.z)) + 3.f;
                g_winpos[cell * CAPW + pos] = make_float4(gp.x, gp.y, gp.z, m2);
                float4 ic = g_icov_s[gi];
                g_winic[cell * CAPW + pos] = make_float4(ic.x, ic.y, ic.z, gp.w);
                g_wincd[cell * CAPW + pos] = cd;
            }
        }
    }
}

// Exact per-query fallback (rare): gmem ring expansion + threshold rescan.
__device__ __noinline__ void fallback_query(int q, float qx, float qy, float qz,
                                            int cx, int cy, int cz,
                                            const float4* __restrict__ feats4,
                                            float* __restrict__ out) {
    const float h = 1.0f / (float)G;
    float bd[KNN];
#pragma unroll
    for (int t = 0; t < KNN; t++) bd[t] = FLT_MAX;

    int rfin = 1;
    for (int r = 1; r <= G; ++r) {
        rfin = r;
        for (int dz = -r; dz <= r; ++dz) {
            int z = cz + dz; if ((unsigned)z >= G) continue;
            for (int dy = -r; dy <= r; ++dy) {
                int y = cy + dy; if ((unsigned)y >= G) continue;
                bool edge = (dz == -r) | (dz == r) | (dy == -r) | (dy == r);
                int step = (r > 1 && !edge) ? 2 * r : 1;
                for (int dx = -r; dx <= r; dx += step) {
                    int x = cx + dx; if ((unsigned)x >= G) continue;
                    int cid = (z * G + y) * G + x;
                    int c0 = g_start[cid], c1 = g_start[cid + 1];
                    for (int c = c0; c < c1; ++c) {
                        float4 g = g_sorted[c];
                        float ddx = qx - g.x, ddy = qy - g.y, ddz = qz - g.z;
                        float d2 = fmaf(ddx, ddx, fmaf(ddy, ddy, ddz * ddz));
                        if (d2 < bd[0]) {
                            bd[0] = d2;
#pragma unroll
                            for (int t = 0; t < KNN - 1; t++) {
                                float a = fmaxf(bd[t], bd[t+1]);
                                float b = fminf(bd[t], bd[t+1]);
                                bd[t] = a; bd[t+1] = b;
                            }
                        }
                    }
                }
            }
        }
        float m = 1e30f;
        if (cx - r > 0)     m = fminf(m, qx - (float)(cx - r) * h);
        if (cx + r < G - 1) m = fminf(m, (float)(cx + r + 1) * h - qx);
        if (cy - r > 0)     m = fminf(m, qy - (float)(cy - r) * h);
        if (cy + r < G - 1) m = fminf(m, (float)(cy + r + 1) * h - qy);
        if (cz - r > 0)     m = fminf(m, qz - (float)(cz - r) * h);
        if (cz + r < G - 1) m = fminf(m, (float)(cz + r + 1) * h - qz);
        if (bd[0] <= m * m) break;
    }
    const float T = bd[0];

    int myp[KNN];
#pragma unroll
    for (int t = 0; t < KNN; t++) myp[t] = 0;
    int cnt = 0;
    {
        const int r = rfin;
        for (int dz = -r; dz <= r; ++dz) {
            int z = cz + dz; if ((unsigned)z >= G) continue;
            for (int dy = -r; dy <= r; ++dy) {
                int y = cy + dy; if ((unsigned)y >= G) continue;
                for (int dx = -r; dx <= r; ++dx) {
                    int x = cx + dx; if ((unsigned)x >= G) continue;
                    int cid = (z * G + y) * G + x;
                    int c0 = g_start[cid], c1 = g_start[cid + 1];
                    for (int c = c0; c < c1; ++c) {
                        float4 g = g_sorted[c];
                        float ddx = qx - g.x, ddy = qy - g.y, ddz = qz - g.z;
                        float d2 = fmaf(ddx, ddx, fmaf(ddy, ddy, ddz * ddz));
                        if (d2 <= T && cnt < KNN) { myp[cnt] = c; cnt++; }
                    }
                }
            }
        }
    }

    float acc[NF];
#pragma unroll
    for (int f = 0; f < NF; f++) acc[f] = 0.f;
    float wsum = 0.f;
#pragma unroll
    for (int t = 0; t < KNN; t++) {
        int p = myp[t];
        float4 g = g_sorted[p];
        float4 ic = g_icov_s[p];
        int id = __float_as_int(g.w);
        float ddx = qx - g.x, ddy = qy - g.y, ddz = qz - g.z;
        float e = fmaf(ddx*ddx, ic.x, fmaf(ddy*ddy, ic.y, ddz*ddz*ic.z));
        float wgt = __expf(-0.5f * e);
        wsum += wgt;
        const float4* fp = feats4 + (size_t)id * (NF/4);
#pragma unroll
        for (int cc = 0; cc < NF/4; cc++) {
            float4 fv = fp[cc];
            acc[4*cc+0] = fmaf(wgt, fv.x, acc[4*cc+0]);
            acc[4*cc+1] = fmaf(wgt, fv.y, acc[4*cc+1]);
            acc[4*cc+2] = fmaf(wgt, fv.z, acc[4*cc+2]);
            acc[4*cc+3] = fmaf(wgt, fv.w, acc[4*cc+3]);
        }
    }
    float inv = 1.f / (wsum + 1e-8f);
    float4* o4 = (float4*)(out + (size_t)q * NF);
#pragma unroll
    for (int cc = 0; cc < NF/4; cc++)
        o4[cc] = make_float4(acc[4*cc+0]*inv, acc[4*cc+1]*inv,
                             acc[4*cc+2]*inv, acc[4*cc+3]*inv);
}

// Main: SPLITS blocks/cell, 2 threads/query, radially-sorted smem window,
// early exit on center-distance bound, FFMA-only distance compare.
__global__ __launch_bounds__(128, 8)
void splash_cell(const float* __restrict__ coords,
                 const float4* __restrict__ feats4,
                 float* __restrict__ out) {
    __shared__ float4 spos[CAPW];
    __shared__ float scd[CAPW];

    const int cell = blockIdx.x >> 1;
    const int half = blockIdx.x & 1;
    const int q0 = g_qstart[cell], q1 = g_qstart[cell + 1];
    const int qbeg = q0 + half * QCHUNK;
    if (qbeg >= q1) return;

    const int nSW = g_nsw[cell];
    const float wmarg = g_wmargin[cell];

    for (int i = threadIdx.x; i < nSW; i += 128) {
        spos[i] = g_winpos[cell * CAPW + i];
        scd[i] = g_wincd[cell * CAPW + i];
    }
    __syncthreads();

    const int cx = cell & 7, cy = (cell >> 3) & 7, cz = cell >> 6;
    const float ccx = (cx + 0.5f) * 0.125f;
    const float ccy = (cy + 0.5f) * 0.125f;
    const float ccz = (cz + 0.5f) * 0.125f;
    const float h = 0.125f;
    const int r = threadIdx.x & 1;
    const int pair = threadIdx.x >> 1;

    for (int b0 = qbeg; b0 < q1; b0 += SPLITS * QCHUNK) {
        const int qi = b0 + pair;
        const bool has = (qi < q1) && (qi < b0 + QCHUNK);
        const int q = g_qorder[has ? qi : q0];
        const float qx = coords[3*q+0], qy = coords[3*q+1], qz = coords[3*q+2];
        const float qq = fmaf(qx, qx, fmaf(qy, qy, qz * qz));
        const float n2x = -2.f * qx, n2y = -2.f * qy, n2z = -2.f * qz;
        float rdx = qx - ccx, rdy = qy - ccy, rdz = qz - ccz;
        const float rq = sqrtf(fmaf(rdx, rdx, fmaf(rdy, rdy, rdz * rdz)));

        const bool mainable = has && nSW >= 32 && wmarg >= 0.f;

        unsigned key[KNN];
#pragma unroll
        for (int t = 0; t < KNN; t++) key[t] = 0xFFFFFFFFu;

        // Chunked scan with warp-converged early exit.
        bool done = !mainable;
        for (int base = r; ; base += 64) {
            if (!done) {
                int lim = min(base + 64, nSW);
#pragma unroll 4
                for (int j = base; j < lim; j += 2) {
                    float4 g = spos[j];
                    float t = fmaf(g.x, n2x, fmaf(g.y, n2y, fmaf(g.z, n2z, g.w)));
                    unsigned kn = (__float_as_uint(t) & ~IDXMASK) | (unsigned)j;
                    if (kn < key[0]) {
                        key[0] = kn;
#pragma unroll
                        for (int s = 0; s < KNN - 1; s++) {
                            unsigned a = umax(key[s], key[s+1]);
                            unsigned b = umin(key[s], key[s+1]);
                            key[s] = a; key[s+1] = b;
                        }
                    }
                }
                if (base + 64 >= nSW) done = true;
                else {
                    float d16sq = __uint_as_float(key[0] & ~IDXMASK) - 3.f + qq;
                    if (d16sq >= 0.f) {        // NaN (unfilled) -> keep going
                        float dn = sqrtf(d16sq) + rq;
                        if (scd[base + 64] - BWIDTH > dn * dn) done = true;
                    }
                }
            }
            if (__all_sync(0xffffffffu, done)) break;
        }

        // Pair merge: every lane ends up holding all 16 merged keys.
        unsigned c[KNN];
#pragma unroll
        for (int t = 0; t < KNN; t++) {
            unsigned pk = __shfl_xor_sync(0xffffffffu, key[KNN - 1 - t], 1);
            c[t] = umin(key[t], pk);
        }
        unsigned mx = c[0];
#pragma unroll
        for (int t = 1; t < KNN; t++) mx = umax(mx, c[t]);
        float d16sq = __uint_as_float(mx & ~IDXMASK) - 3.f + qq;

        // Validity: face margin AND window-truncation margin.
        float m = 1e30f;
        if (cx - 1 > 0)     m = fminf(m, qx - (float)(cx - 1) * h);
        if (cx + 1 < G - 1) m = fminf(m, (float)(cx + 2) * h - qx);
        if (cy - 1 > 0)     m = fminf(m, qy - (float)(cy - 1) * h);
        if (cy + 1 < G - 1) m = fminf(m, (float)(cy + 2) * h - qy);
        if (cz - 1 > 0)     m = fminf(m, qz - (float)(cz - 1) * h);
        if (cz + 1 < G - 1) m = fminf(m, (float)(cz + 2) * h - qz);

        float d16c = sqrtf(fmaxf(d16sq, 0.f));
        bool ok = mainable && (d16sq <= m * m)
                  && ((d16c + rq) * (d16c + rq) <= wmarg);

        if (has && !ok) {
            if (r == 0) fallback_query(q, qx, qy, qz, cx, cy, cz, feats4, out);
            continue;
        }
        if (!has) continue;

        // Aggregation: each lane computes all 16 weights, accumulates only
        // its own half of the feature vector.
        float acc[NF/2];
#pragma unroll
        for (int f = 0; f < NF/2; f++) acc[f] = 0.f;
        float wsum = 0.f;
#pragma unroll
        for (int t = 0; t < KNN; t++) {
            int p = (int)(c[t] & IDXMASK);
            float4 g = spos[p];
            float4 ic = g_winic[cell * CAPW + p];
            int id = __float_as_int(ic.w);
            float ddx = qx - g.x, ddy = qy - g.y, ddz = qz - g.z;
            float e = fmaf(ddx*ddx, ic.x, fmaf(ddy*ddy, ic.y, ddz*ddz*ic.z));
            float wgt = __expf(-0.5f * e);
            wsum += wgt;
            const float4* fp = feats4 + (size_t)id * (NF/4) + r * (NF/8);
#pragma unroll
            for (int cc = 0; cc < NF/8; cc++) {
                float4 fv = fp[cc];
                acc[4*cc+0] = fmaf(wgt, fv.x, acc[4*cc+0]);
                acc[4*cc+1] = fmaf(wgt, fv.y, acc[4*cc+1]);
                acc[4*cc+2] = fmaf(wgt, fv.z, acc[4*cc+2]);
                acc[4*cc+3] = fmaf(wgt, fv.w, acc[4*cc+3]);
            }
        }
        float inv = 1.f / (wsum + 1e-8f);
        float4* o4 = (float4*)(out + (size_t)q * NF) + r * (NF/8);
#pragma unroll
        for (int cc = 0; cc < NF/8; cc++)
            o4[cc] = make_float4(acc[4*cc+0]*inv, acc[4*cc+1]*inv,
                                 acc[4*cc+2]*inv, acc[4*cc+3]*inv);
    }
}

extern "C" void kernel_launch(void* const* d_in, const int* in_sizes, int n_in,
                              void* d_out, int out_size) {
    const float* coords = (const float*)d_in[0];
    const float* means  = (const float*)d_in[1];
    const float* logc   = (const float*)d_in[2];
    const float* feats  = (const float*)d_in[3];
    float* out = (float*)d_out;

    int M = in_sizes[0] / 3;
    int N = in_sizes[1] / 3;
    int mx = (M > N ? M : N);

    k_hist<<<(mx + 255) / 256, 256>>>(means, N, coords, M);
    k_scan<<<1, NC>>>();
    k_scatter<<<(mx + 255) / 256, 256>>>(means, logc, N, M);
    k_window<<<NC, 128>>>();
    splash_cell<<<NC * SPLITS, 128>>>(coords, (const float4*)feats, out);
}

// round 8
// speedup vs baseline: 1.4490x; 1.0050x over previous
#include <cuda_runtime.h>
#include <math.h>
#include <float.h>

#define G 8
#define NC (G*G*G)
#define MAXN 10016
#define MAXM 32768
#define KNN 16
#define NF 32
#define CAPW 512
#define WMAX 1024
#define NBKT 32
#define KD 12               // per-lane top-K depth (padded to 16 at merge)
#define IDXMASK 0x1FFu
#define CDMAX 0.1055f
#define BWIDTH (CDMAX / (float)NBKT)
#define INVBW ((float)NBKT / CDMAX)

// ---- device scratch (allocation-free) ----
__device__ float4 g_sorted[MAXN];
__device__ float4 g_icov_s[MAXN];
__device__ int g_cnt[NC], g_start[NC + 1];
__device__ int g_qcnt[NC], g_qstart[NC + 1];
__device__ int g_gcell[MAXN], g_grank[MAXN];
__device__ int g_qcell[MAXM], g_qrank[MAXM];
__device__ int g_qorder[MAXM];
__device__ float4 g_winpos[NC * CAPW]; // (x,y,z, |m|^2+3)
__device__ float4 g_winic[NC * CAPW];  // (icx,icy,icz, orig-id bits)
__device__ float  g_wincd[NC * CAPW];  // center-dist^2
__device__ float  g_wmargin[NC];
__device__ int    g_nsw[NC];

__device__ __forceinline__ int cell_coord(float v) {
    int c = (int)(v * (float)G);
    return min(G - 1, max(0, c));
}

__global__ void k_hist(const float* __restrict__ means, int N,
                       const float* __restrict__ coords, int M) {
    int i = blockIdx.x * blockDim.x + threadIdx.x;
    if (i < N) {
        int c = (cell_coord(means[3*i+2]) * G + cell_coord(means[3*i+1])) * G
                + cell_coord(means[3*i+0]);
        g_gcell[i] = c;
        g_grank[i] = atomicAdd(&g_cnt[c], 1);
    }
    if (i < M) {
        int c = (cell_coord(coords[3*i+2]) * G + cell_coord(coords[3*i+1])) * G
                + cell_coord(coords[3*i+0]);
        g_qcell[i] = c;
        g_qrank[i] = atomicAdd(&g_qcnt[c], 1);
    }
}

__global__ void k_scan() {
    __shared__ int ws[16];
    int t = threadIdx.x, lane = t & 31, w = t >> 5;

    int s = g_cnt[t];
    g_cnt[t] = 0;
    for (int o = 1; o < 32; o <<= 1) {
        int u = __shfl_up_sync(0xffffffffu, s, o);
        if (lane >= o) s += u;
    }
    if (lane == 31) ws[w] = s;
    __syncthreads();
    if (t < 32) {
        int v = (t < 16) ? ws[t] : 0;
        for (int o = 1; o < 16; o <<= 1) {
            int u = __shfl_up_sync(0xffffffffu, v, o);
            if (t >= o) v += u;
        }
        if (t < 16) ws[t] = v;
    }
    __syncthreads();
    g_start[t + 1] = (w ? ws[w - 1] : 0) + s;
    if (t == 0) g_start[0] = 0;
    __syncthreads();

    s = g_qcnt[t];
    g_qcnt[t] = 0;
    for (int o = 1; o < 32; o <<= 1) {
        int u = __shfl_up_sync(0xffffffffu, s, o);
        if (lane >= o) s += u;
    }
    if (lane == 31) ws[w] = s;
    __syncthreads();
    if (t < 32) {
        int v = (t < 16) ? ws[t] : 0;
        for (int o = 1; o < 16; o <<= 1) {
            int u = __shfl_up_sync(0xffffffffu, v, o);
            if (t >= o) v += u;
        }
        if (t < 16) ws[t] = v;
    }
    __syncthreads();
    g_qstart[t + 1] = (w ? ws[w - 1] : 0) + s;
    if (t == 0) g_qstart[0] = 0;
}

__global__ void k_scatter(const float* __restrict__ means,
                          const float* __restrict__ logc, int N, int M) {
    int i = blockIdx.x * blockDim.x + threadIdx.x;
    if (i < N) {
        int pos = g_start[g_gcell[i]] + g_grank[i];
        g_sorted[pos] = make_float4(means[3*i], means[3*i+1], means[3*i+2],
                                    __int_as_float(i));
        g_icov_s[pos] = make_float4(expf(-logc[3*i]), expf(-logc[3*i+1]),
                                    expf(-logc[3*i+2]), 0.f);
    }
    if (i < M) {
        int pos = g_qstart[g_qcell[i]] + g_qrank[i];
        g_qorder[pos] = i;
    }
}

// Per-cell radially-ordered window build (bucket counting sort by center dist).
__global__ __launch_bounds__(256)
void k_window() {
    __shared__ float skey[WMAX];
    __shared__ int   sgid[WMAX];
    __shared__ int   cnt[NBKT], st[NBKT + 1], fil[NBKT];

    const int cell = blockIdx.x, tid = threadIdx.x;
    const int cx = cell & 7, cy = (cell >> 3) & 7, cz = cell >> 6;
    const float ccx = (cx + 0.5f) * 0.125f;
    const float ccy = (cy + 0.5f) * 0.125f;
    const float ccz = (cz + 0.5f) * 0.125f;

    if (tid < NBKT) { cnt[tid] = 0; fil[tid] = 0; }
    __syncthreads();

    const int x0 = max(cx - 1, 0), x1e = min(cx + 1, G - 1) + 1;
    int n = 0;
    bool ovf = false;
    for (int z = max(cz - 1, 0); z <= min(cz + 1, G - 1); ++z) {
        for (int y = max(cy - 1, 0); y <= min(cy + 1, G - 1); ++y) {
            int base = (z * G + y) * G;
            int r0 = g_start[base + x0];
            int len = g_start[base + x1e] - r0;
            if (ovf || n + len > WMAX) { ovf = true; continue; }
            for (int i = tid; i < len; i += 256) {
                float4 g = g_sorted[r0 + i];
                float dx = g.x - ccx, dy = g.y - ccy, dz = g.z - ccz;
                float cd = fmaf(dx, dx, fmaf(dy, dy, dz * dz));
                skey[n + i] = cd;
                sgid[n + i] = r0 + i;
                atomicAdd(&cnt[min(NBKT - 1, (int)(cd * INVBW))], 1);
            }
            n += len;
        }
    }
    __syncthreads();

    if (tid < 32) {
        int v = cnt[tid];
        for (int o = 1; o < 32; o <<= 1) {
            int u = __shfl_up_sync(0xffffffffu, v, o);
            if (tid >= o) v += u;
        }
        st[tid + 1] = v;
        if (tid == 0) st[0] = 0;
    }
    __syncthreads();

    if (tid == 0) {
        int nsw = min(n, CAPW);
        float marg = 1e30f;
        if (ovf) { marg = -1.f; nsw = 0; }
        else if (n > CAPW) {
            int t = 0;
            while (t < NBKT && st[t + 1] <= CAPW) t++;
            marg = (float)t * BWIDTH;
        }
        g_wmargin[cell] = marg;
        g_nsw[cell] = nsw;
    }
    __syncthreads();

    if (!ovf) {
        for (int i = tid; i < n; i += 256) {
            float cd = skey[i];
            int b = min(NBKT - 1, (int)(cd * INVBW));
            int pos = st[b] + atomicAdd(&fil[b], 1);
            if (pos < CAPW) {
                int gi = sgid[i];
                float4 gp = g_sorted[gi];
                float m2 = fmaf(gp.x, gp.x, fmaf(gp.y, gp.y, gp.z * gp.z)) + 3.f;
                g_winpos[cell * CAPW + pos] = make_float4(gp.x, gp.y, gp.z, m2);
                float4 ic = g_icov_s[gi];
                g_winic[cell * CAPW + pos] = make_float4(ic.x, ic.y, ic.z, gp.w);
                g_wincd[cell * CAPW + pos] = cd;
            }
        }
    }
}

// Exact per-query fallback (rare).
__device__ __noinline__ void fallback_query(int q, float qx, float qy, float qz,
                                            int cx, int cy, int cz,
                                            const float4* __restrict__ feats4,
                                            float* __restrict__ out) {
    const float h = 1.0f / (float)G;
    float bd[KNN];
#pragma unroll
    for (int t = 0; t < KNN; t++) bd[t] = FLT_MAX;

    int rfin = 1;
    for (int r = 1; r <= G; ++r) {
        rfin = r;
        for (int dz = -r; dz <= r; ++dz) {
            int z = cz + dz; if ((unsigned)z >= G) continue;
            for (int dy = -r; dy <= r; ++dy) {
                int y = cy + dy; if ((unsigned)y >= G) continue;
                bool edge = (dz == -r) | (dz == r) | (dy == -r) | (dy == r);
                int step = (r > 1 && !edge) ? 2 * r : 1;
                for (int dx = -r; dx <= r; dx += step) {
                    int x = cx + dx; if ((unsigned)x >= G) continue;
                    int cid = (z * G + y) * G + x;
                    int c0 = g_start[cid], c1 = g_start[cid + 1];
                    for (int c = c0; c < c1; ++c) {
                        float4 g = g_sorted[c];
                        float ddx = qx - g.x, ddy = qy - g.y, ddz = qz - g.z;
                        float d2 = fmaf(ddx, ddx, fmaf(ddy, ddy, ddz * ddz));
                        if (d2 < bd[0]) {
                            bd[0] = d2;
#pragma unroll
                            for (int t = 0; t < KNN - 1; t++) {
                                float a = fmaxf(bd[t], bd[t+1]);
                                float b = fminf(bd[t], bd[t+1]);
                                bd[t] = a; bd[t+1] = b;
                            }
                        }
                    }
                }
            }
        }
        float m = 1e30f;
        if (cx - r > 0)     m = fminf(m, qx - (float)(cx - r) * h);
        if (cx + r < G - 1) m = fminf(m, (float)(cx + r + 1) * h - qx);
        if (cy - r > 0)     m = fminf(m, qy - (float)(cy - r) * h);
        if (cy + r < G - 1) m = fminf(m, (float)(cy + r + 1) * h - qy);
        if (cz - r > 0)     m = fminf(m, qz - (float)(cz - r) * h);
        if (cz + r < G - 1) m = fminf(m, (float)(cz + r + 1) * h - qz);
        if (bd[0] <= m * m) break;
    }
    const float T = bd[0];

    int myp[KNN];
#pragma unroll
    for (int t = 0; t < KNN; t++) myp[t] = 0;
    int cnt = 0;
    {
        const int r = rfin;
        for (int dz = -r; dz <= r; ++dz) {
            int z = cz + dz; if ((unsigned)z >= G) continue;
            for (int dy = -r; dy <= r; ++dy) {
                int y = cy + dy; if ((unsigned)y >= G) continue;
                for (int dx = -r; dx <= r; ++dx) {
                    int x = cx + dx; if ((unsigned)x >= G) continue;
                    int cid = (z * G + y) * G + x;
                    int c0 = g_start[cid], c1 = g_start[cid + 1];
                    for (int c = c0; c < c1; ++c) {
                        float4 g = g_sorted[c];
                        float ddx = qx - g.x, ddy = qy - g.y, ddz = qz - g.z;
                        float d2 = fmaf(ddx, ddx, fmaf(ddy, ddy, ddz * ddz));
                        if (d2 <= T && cnt < KNN) { myp[cnt] = c; cnt++; }
                    }
                }
            }
        }
    }

    float acc[NF];
#pragma unroll
    for (int f = 0; f < NF; f++) acc[f] = 0.f;
    float wsum = 0.f;
#pragma unroll
    for (int t = 0; t < KNN; t++) {
        int p = myp[t];
        float4 g = g_sorted[p];
        float4 ic = g_icov_s[p];
        int id = __float_as_int(g.w);
        float ddx = qx - g.x, ddy = qy - g.y, ddz = qz - g.z;
        float e = fmaf(ddx*ddx, ic.x, fmaf(ddy*ddy, ic.y, ddz*ddz*ic.z));
        float wgt = __expf(-0.5f * e);
        wsum += wgt;
        const float4* fp = feats4 + (size_t)id * (NF/4);
#pragma unroll
        for (int cc = 0; cc < NF/4; cc++) {
            float4 fv = fp[cc];
            acc[4*cc+0] = fmaf(wgt, fv.x, acc[4*cc+0]);
            acc[4*cc+1] = fmaf(wgt, fv.y, acc[4*cc+1]);
            acc[4*cc+2] = fmaf(wgt, fv.z, acc[4*cc+2]);
            acc[4*cc+3] = fmaf(wgt, fv.w, acc[4*cc+3]);
        }
    }
    float inv = 1.f / (wsum + 1e-8f);
    float4* o4 = (float4*)(out + (size_t)q * NF);
#pragma unroll
    for (int cc = 0; cc < NF/4; cc++)
        o4[cc] = make_float4(acc[4*cc+0]*inv, acc[4*cc+1]*inv,
                             acc[4*cc+2]*inv, acc[4*cc+3]*inv);
}

// Main: 4 lanes per query, 8 queries per warp, no smem, windows via L1.
__global__ __launch_bounds__(128, 7)
void splash_q(const float* __restrict__ coords,
              const float4* __restrict__ feats4,
              float* __restrict__ out, int M) {
    const int gw = (blockIdx.x * blockDim.x + threadIdx.x) >> 5;
    const int lane = threadIdx.x & 31;
    const int L = lane & 3;
    const int qslot = gw * 8 + (lane >> 2);
    const bool has = qslot < M;

    const int q = g_qorder[has ? qslot : 0];
    const float qx = coords[3*q+0], qy = coords[3*q+1], qz = coords[3*q+2];
    const int cx = cell_coord(qx), cy = cell_coord(qy), cz = cell_coord(qz);
    const int cell = (cz * G + cy) * G + cx;
    const int cb = cell * CAPW;
    const int nSW = g_nsw[cell];
    const float wmarg = g_wmargin[cell];

    const float qq = fmaf(qx, qx, fmaf(qy, qy, qz * qz));
    const float n2x = -2.f * qx, n2y = -2.f * qy, n2z = -2.f * qz;
    const float ccx = (cx + 0.5f) * 0.125f;
    const float ccy = (cy + 0.5f) * 0.125f;
    const float ccz = (cz + 0.5f) * 0.125f;
    float rdx = qx - ccx, rdy = qy - ccy, rdz = qz - ccz;
    const float rq = sqrtf(fmaf(rdx, rdx, fmaf(rdy, rdy, rdz * rdz)));

    const bool mainable = has && nSW >= 32 && wmarg >= 0.f;

    // Per-lane top-KD (descending keys; key[0] = worst kept).
    unsigned key[KD];
#pragma unroll
    for (int t = 0; t < KD; t++) key[t] = 0xFFFFFFFFu;

    bool done = !mainable;
    for (int base = 0; ; base += 32) {
        if (!done) {
            int lim = min(base + 32, nSW);
#pragma unroll
            for (int k = 0; k < 8; k++) {
                int j = base + L + 4 * k;
                if (j < lim) {
                    float4 g = __ldg(&g_winpos[cb + j]);
                    float t = fmaf(g.x, n2x, fmaf(g.y, n2y, fmaf(g.z, n2z, g.w)));
                    unsigned kn = (__float_as_uint(t) & ~IDXMASK) | (unsigned)j;
                    if (kn < key[0]) {
                        key[0] = kn;
#pragma unroll
                        for (int s = 0; s < KD - 1; s++) {
                            unsigned a = umax(key[s], key[s+1]);
                            unsigned b = umin(key[s], key[s+1]);
                            key[s] = a; key[s+1] = b;
                        }
                    }
                }
            }
            if (base + 32 >= nSW) done = true;
            else {
                float d16sq = __uint_as_float(key[0] & ~IDXMASK) - 3.f + qq;
                if (d16sq >= 0.f) {   // NaN/unfilled fails -> keep scanning
                    float dn = sqrtf(d16sq) + rq;
                    if (__ldg(&g_wincd[cb + base + 32]) - BWIDTH > dn * dn)
                        done = true;
                }
            }
        }
        if (__all_sync(0xffffffffu, done)) break;
    }

    // Pad to 16 (descending: pads first), then two-stage exact merge.
    unsigned pe[16];
#pragma unroll
    for (int t = 0; t < 4; t++) pe[t] = 0xFFFFFFFFu;
#pragma unroll
    for (int t = 0; t < KD; t++) pe[4 + t] = key[t];

    // Stage 1 (xor 1): 16 smallest of 32 via min-trick -> bitonic e[].
    unsigned e[16];
#pragma unroll
    for (int t = 0; t < 16; t++) {
        unsigned pp = __shfl_xor_sync(0xffffffffu, pe[15 - t], 1);
        e[t] = umin(pe[t], pp);
    }
    // Bitonic merge: sort descending (4 stages).
#define CE_(i, j) { unsigned a_ = umax(e[i], e[j]); unsigned b_ = umin(e[i], e[j]); e[i] = a_; e[j] = b_; }
#pragma unroll
    for (int i = 0; i < 8; i++) CE_(i, i + 8);
#pragma unroll
    for (int hbase = 0; hbase < 16; hbase += 8)
#pragma unroll
        for (int i = 0; i < 4; i++) CE_(hbase + i, hbase + i + 4);
#pragma unroll
    for (int hbase = 0; hbase < 16; hbase += 4)
#pragma unroll
        for (int i = 0; i < 2; i++) CE_(hbase + i, hbase + i + 2);
#pragma unroll
    for (int i = 0; i < 16; i += 2) CE_(i, i + 1);
#undef CE_

    // Stage 2 (xor 2): 16 smallest of 64.
    unsigned gk[16];
#pragma unroll
    for (int t = 0; t < 16; t++) {
        unsigned pp = __shfl_xor_sync(0xffffffffu, e[15 - t], 2);
        gk[t] = umin(e[t], pp);
    }
    unsigned mx = gk[0];
#pragma unroll
    for (int t = 1; t < 16; t++) mx = umax(mx, gk[t]);

    // Safety: no lane may have dropped/skipped anything below the global 16th.
    bool lane_ok = (key[0] >= mx);
    unsigned bal = __ballot_sync(0xffffffffu, lane_ok);
    bool quad_ok = (((bal >> (lane & ~3)) & 0xFu) == 0xFu);

    float d16sq = __uint_as_float(mx & ~IDXMASK) - 3.f + qq;
    const float h = 0.125f;
    float m = 1e30f;
    if (cx - 1 > 0)     m = fminf(m, qx - (float)(cx - 1) * h);
    if (cx + 1 < G - 1) m = fminf(m, (float)(cx + 2) * h - qx);
    if (cy - 1 > 0)     m = fminf(m, qy - (float)(cy - 1) * h);
    if (cy + 1 < G - 1) m = fminf(m, (float)(cy + 2) * h - qy);
    if (cz - 1 > 0)     m = fminf(m, qz - (float)(cz - 1) * h);
    if (cz + 1 < G - 1) m = fminf(m, (float)(cz + 2) * h - qz);

    float d16c = sqrtf(fmaxf(d16sq, 0.f));
    bool ok = mainable && quad_ok && (d16sq <= m * m)
              && ((d16c + rq) * (d16c + rq) <= wmarg);

    if (has && !ok) {
        if (L == 0) fallback_query(q, qx, qy, qz, cx, cy, cz, feats4, out);
        return;
    }
    if (!has) return;

    // Aggregation: all 16 weights per lane; each lane owns 8 features.
    float acc[NF/4];
#pragma unroll
    for (int f = 0; f < NF/4; f++) acc[f] = 0.f;
    float wsum = 0.f;
#pragma unroll
    for (int t = 0; t < KNN; t++) {
        int p = (int)(gk[t] & IDXMASK);
        float4 g = __ldg(&g_winpos[cb + p]);
        float4 ic = __ldg(&g_winic[cb + p]);
        int id = __float_as_int(ic.w);
        float ddx = qx - g.x, ddy = qy - g.y, ddz = qz - g.z;
        float e2 = fmaf(ddx*ddx, ic.x, fmaf(ddy*ddy, ic.y, ddz*ddz*ic.z));
        float wgt = __expf(-0.5f * e2);
        wsum += wgt;
        const float4* fp = feats4 + (size_t)id * (NF/4) + L * 2;
        float4 f0 = __ldg(&fp[0]);
        float4 f1 = __ldg(&fp[1]);
        acc[0] = fmaf(wgt, f0.x, acc[0]);
        acc[1] = fmaf(wgt, f0.y, acc[1]);
        acc[2] = fmaf(wgt, f0.z, acc[2]);
        acc[3] = fmaf(wgt, f0.w, acc[3]);
        acc[4] = fmaf(wgt, f1.x, acc[4]);
        acc[5] = fmaf(wgt, f1.y, acc[5]);
        acc[6] = fmaf(wgt, f1.z, acc[6]);
        acc[7] = fmaf(wgt, f1.w, acc[7]);
    }
    float inv = 1.f / (wsum + 1e-8f);
    float4* o4 = (float4*)(out + (size_t)q * NF) + L * 2;
    o4[0] = make_float4(acc[0]*inv, acc[1]*inv, acc[2]*inv, acc[3]*inv);
    o4[1] = make_float4(acc[4]*inv, acc[5]*inv, acc[6]*inv, acc[7]*inv);
}

extern "C" void kernel_launch(void* const* d_in, const int* in_sizes, int n_in,
                              void* d_out, int out_size) {
    const float* coords = (const float*)d_in[0];
    const float* means  = (const float*)d_in[1];
    const float* logc   = (const float*)d_in[2];
    const float* feats  = (const float*)d_in[3];
    float* out = (float*)d_out;

    int M = in_sizes[0] / 3;
    int N = in_sizes[1] / 3;
    int mx = (M > N ? M : N);

    k_hist<<<(mx + 255) / 256, 256>>>(means, N, coords, M);
    k_scan<<<1, NC>>>();
    k_scatter<<<(mx + 255) / 256, 256>>>(means, logc, N, M);
    k_window<<<NC, 256>>>();
    int qblocks = (M * 4 + 127) / 128;
    splash_q<<<qblocks, 128>>>(coords, (const float4*)feats, out, M);
}

// round 9
// speedup vs baseline: 1.9381x; 1.3376x over previous
#include <cuda_runtime.h>
#include <math.h>
#include <float.h>

#define G 8
#define NC (G*G*G)
#define MAXN 10016
#define MAXM 32768
#define KNN 16
#define NF 32
#define CAPW 512
#define WMAX 1024
#define NBKT 32
#define KD 12
#define IDXMASK 0x1FFu
#define CDMAX 0.1055f
#define BWIDTH (CDMAX / (float)NBKT)
#define INVBW ((float)NBKT / CDMAX)

// ---- device scratch (allocation-free) ----
__device__ float4 g_sorted[MAXN];
__device__ float4 g_icov_s[MAXN];
__device__ int g_cnt[NC], g_start[NC + 1];
__device__ int g_qcnt[NC], g_qstart[NC + 1];
__device__ int g_gcell[MAXN], g_grank[MAXN];
__device__ int g_qcell[MAXM], g_qrank[MAXM];
__device__ int g_qorder[MAXM];
__device__ float4 g_winpos[NC * CAPW]; // (x,y,z, |m|^2+3); pads = sentinels
__device__ float4 g_winic[NC * CAPW];  // (icx,icy,icz, orig-id bits)
__device__ float  g_wincd[NC * CAPW];  // center-dist^2; pads = 1e30
__device__ float  g_wmargin[NC];
__device__ int    g_nsw[NC];           // real window count
__device__ int    g_nswp[NC];          // padded (multiple of 32)

__device__ __forceinline__ int cell_coord(float v) {
    int c = (int)(v * (float)G);
    return min(G - 1, max(0, c));
}

__global__ void k_hist(const float* __restrict__ means, int N,
                       const float* __restrict__ coords, int M) {
    int i = blockIdx.x * blockDim.x + threadIdx.x;
    if (i < N) {
        int c = (cell_coord(means[3*i+2]) * G + cell_coord(means[3*i+1])) * G
                + cell_coord(means[3*i+0]);
        g_gcell[i] = c;
        g_grank[i] = atomicAdd(&g_cnt[c], 1);
    }
    if (i < M) {
        int c = (cell_coord(coords[3*i+2]) * G + cell_coord(coords[3*i+1])) * G
                + cell_coord(coords[3*i+0]);
        g_qcell[i] = c;
        g_qrank[i] = atomicAdd(&g_qcnt[c], 1);
    }
}

__global__ void k_scan() {
    __shared__ int ws[16];
    int t = threadIdx.x, lane = t & 31, w = t >> 5;

    int s = g_cnt[t];
    g_cnt[t] = 0;
    for (int o = 1; o < 32; o <<= 1) {
        int u = __shfl_up_sync(0xffffffffu, s, o);
        if (lane >= o) s += u;
    }
    if (lane == 31) ws[w] = s;
    __syncthreads();
    if (t < 32) {
        int v = (t < 16) ? ws[t] : 0;
        for (int o = 1; o < 16; o <<= 1) {
            int u = __shfl_up_sync(0xffffffffu, v, o);
            if (t >= o) v += u;
        }
        if (t < 16) ws[t] = v;
    }
    __syncthreads();
    g_start[t + 1] = (w ? ws[w - 1] : 0) + s;
    if (t == 0) g_start[0] = 0;
    __syncthreads();

    s = g_qcnt[t];
    g_qcnt[t] = 0;
    for (int o = 1; o < 32; o <<= 1) {
        int u = __shfl_up_sync(0xffffffffu, s, o);
        if (lane >= o) s += u;
    }
    if (lane == 31) ws[w] = s;
    __syncthreads();
    if (t < 32) {
        int v = (t < 16) ? ws[t] : 0;
        for (int o = 1; o < 16; o <<= 1) {
            int u = __shfl_up_sync(0xffffffffu, v, o);
            if (t >= o) v += u;
        }
        if (t < 16) ws[t] = v;
    }
    __syncthreads();
    g_qstart[t + 1] = (w ? ws[w - 1] : 0) + s;
    if (t == 0) g_qstart[0] = 0;
}

__global__ void k_scatter(const float* __restrict__ means,
                          const float* __restrict__ logc, int N, int M) {
    int i = blockIdx.x * blockDim.x + threadIdx.x;
    if (i < N) {
        int pos = g_start[g_gcell[i]] + g_grank[i];
        g_sorted[pos] = make_float4(means[3*i], means[3*i+1], means[3*i+2],
                                    __int_as_float(i));
        g_icov_s[pos] = make_float4(expf(-logc[3*i]), expf(-logc[3*i+1]),
                                    expf(-logc[3*i+2]), 0.f);
    }
    if (i < M) {
        int pos = g_qstart[g_qcell[i]] + g_qrank[i];
        g_qorder[pos] = i;
    }
}

// Per-cell radially-ordered window (bucket counting sort by center dist).
// Flattened gather: 9 row ranges in smem, fully parallel index mapping.
__global__ __launch_bounds__(256)
void k_window() {
    __shared__ float skey[WMAX];
    __shared__ int   sgid[WMAX];
    __shared__ int   cnt[NBKT], st[NBKT + 1], fil[NBKT];
    __shared__ int   rr0[9], roff[10], rcnt_s;

    const int cell = blockIdx.x, tid = threadIdx.x;
    const int cx = cell & 7, cy = (cell >> 3) & 7, cz = cell >> 6;
    const float ccx = (cx + 0.5f) * 0.125f;
    const float ccy = (cy + 0.5f) * 0.125f;
    const float ccz = (cz + 0.5f) * 0.125f;

    if (tid < NBKT) { cnt[tid] = 0; fil[tid] = 0; }

    const int x0 = max(cx - 1, 0), x1e = min(cx + 1, G - 1) + 1;
    if (tid == 0) {
        int rc = 0, n0 = 0;
        for (int z = max(cz - 1, 0); z <= min(cz + 1, G - 1); ++z) {
            for (int y = max(cy - 1, 0); y <= min(cy + 1, G - 1); ++y) {
                int base = (z * G + y) * G;
                int r0 = g_start[base + x0];
                int len = g_start[base + x1e] - r0;
                rr0[rc] = r0; roff[rc] = n0;
                n0 += len; rc++;
            }
        }
        roff[rc] = n0;
        rcnt_s = rc;
    }
    __syncthreads();

    const int rcnt = rcnt_s;
    const int n = roff[rcnt];
    const bool ovf = (n > WMAX);

    if (!ovf) {
        for (int i = tid; i < n; i += 256) {
            int k = 0;
#pragma unroll
            for (int kk = 1; kk < 9; kk++)
                if (kk < rcnt && i >= roff[kk]) k = kk;
            int src = rr0[k] + (i - roff[k]);
            float4 g = g_sorted[src];
            float dx = g.x - ccx, dy = g.y - ccy, dz = g.z - ccz;
            float cd = fmaf(dx, dx, fmaf(dy, dy, dz * dz));
            skey[i] = cd;
            sgid[i] = src;
            atomicAdd(&cnt[min(NBKT - 1, (int)(cd * INVBW))], 1);
        }
    }
    __syncthreads();

    if (tid < 32) {
        int v = cnt[tid];
        for (int o = 1; o < 32; o <<= 1) {
            int u = __shfl_up_sync(0xffffffffu, v, o);
            if (tid >= o) v += u;
        }
        st[tid + 1] = v;
        if (tid == 0) st[0] = 0;
    }
    __syncthreads();

    int nsw = min(n, CAPW);
    if (ovf) nsw = 0;
    const int nswp = min(CAPW, (nsw + 31) & ~31);

    if (tid == 0) {
        float marg = 1e30f;
        if (ovf) marg = -1.f;
        else if (n > CAPW) {
            int t = 0;
            while (t < NBKT && st[t + 1] <= CAPW) t++;
            marg = (float)t * BWIDTH;
        }
        g_wmargin[cell] = marg;
        g_nsw[cell] = nsw;
        g_nswp[cell] = nswp;
    }
    __syncthreads();

    if (!ovf) {
        for (int i = tid; i < n; i += 256) {
            float cd = skey[i];
            int b = min(NBKT - 1, (int)(cd * INVBW));
            int pos = st[b] + atomicAdd(&fil[b], 1);
            if (pos < CAPW) {
                int gi = sgid[i];
                float4 gp = g_sorted[gi];
                float m2 = fmaf(gp.x, gp.x, fmaf(gp.y, gp.y, gp.z * gp.z)) + 3.f;
                g_winpos[cell * CAPW + pos] = make_float4(gp.x, gp.y, gp.z, m2);
                float4 ic = g_icov_s[gi];
                g_winic[cell * CAPW + pos] = make_float4(ic.x, ic.y, ic.z, gp.w);
                g_wincd[cell * CAPW + pos] = cd;
            }
        }
        // Sentinel pads: huge distance, finite values.
        for (int i = nsw + tid; i < nswp; i += 256) {
            g_winpos[cell * CAPW + i] = make_float4(64.f, 64.f, 64.f,
                                                    3.f * 64.f * 64.f + 3.f);
            g_winic[cell * CAPW + i] = make_float4(0.f, 0.f, 0.f,
                                                   __int_as_float(0));
            g_wincd[cell * CAPW + i] = 1e30f;
        }
    }
}

// Exact per-query fallback (rare).
__device__ __noinline__ void fallback_query(int q, float qx, float qy, float qz,
                                            int cx, int cy, int cz,
                                            const float4* __restrict__ feats4,
                                            float* __restrict__ out) {
    const float h = 1.0f / (float)G;
    float bd[KNN];
#pragma unroll
    for (int t = 0; t < KNN; t++) bd[t] = FLT_MAX;

    int rfin = 1;
    for (int r = 1; r <= G; ++r) {
        rfin = r;
        for (int dz = -r; dz <= r; ++dz) {
            int z = cz + dz; if ((unsigned)z >= G) continue;
            for (int dy = -r; dy <= r; ++dy) {
                int y = cy + dy; if ((unsigned)y >= G) continue;
                bool edge = (dz == -r) | (dz == r) | (dy == -r) | (dy == r);
                int step = (r > 1 && !edge) ? 2 * r : 1;
                for (int dx = -r; dx <= r; dx += step) {
                    int x = cx + dx; if ((unsigned)x >= G) continue;
                    int cid = (z * G + y) * G + x;
                    int c0 = g_start[cid], c1 = g_start[cid + 1];
                    for (int c = c0; c < c1; ++c) {
                        float4 g = g_sorted[c];
                        float ddx = qx - g.x, ddy = qy - g.y, ddz = qz - g.z;
                        float d2 = fmaf(ddx, ddx, fmaf(ddy, ddy, ddz * ddz));
                        if (d2 < bd[0]) {
                            bd[0] = d2;
#pragma unroll
                            for (int t = 0; t < KNN - 1; t++) {
                                float a = fmaxf(bd[t], bd[t+1]);
                                float b = fminf(bd[t], bd[t+1]);
                                bd[t] = a; bd[t+1] = b;
                            }
                        }
                    }
                }
            }
        }
        float m = 1e30f;
        if (cx - r > 0)     m = fminf(m, qx - (float)(cx - r) * h);
        if (cx + r < G - 1) m = fminf(m, (float)(cx + r + 1) * h - qx);
        if (cy - r > 0)     m = fminf(m, qy - (float)(cy - r) * h);
        if (cy + r < G - 1) m = fminf(m, (float)(cy + r + 1) * h - qy);
        if (cz - r > 0)     m = fminf(m, qz - (float)(cz - r) * h);
        if (cz + r < G - 1) m = fminf(m, (float)(cz + r + 1) * h - qz);
        if (bd[0] <= m * m) break;
    }
    const float T = bd[0];

    int myp[KNN];
#pragma unroll
    for (int t = 0; t < KNN; t++) myp[t] = 0;
    int cnt = 0;
    {
        const int r = rfin;
        for (int dz = -r; dz <= r; ++dz) {
            int z = cz + dz; if ((unsigned)z >= G) continue;
            for (int dy = -r; dy <= r; ++dy) {
                int y = cy + dy; if ((unsigned)y >= G) continue;
                for (int dx = -r; dx <= r; ++dx) {
                    int x = cx + dx; if ((unsigned)x >= G) continue;
                    int cid = (z * G + y) * G + x;
                    int c0 = g_start[cid], c1 = g_start[cid + 1];
                    for (int c = c0; c < c1; ++c) {
                        float4 g = g_sorted[c];
                        float ddx = qx - g.x, ddy = qy - g.y, ddz = qz - g.z;
                        float d2 = fmaf(ddx, ddx, fmaf(ddy, ddy, ddz * ddz));
                        if (d2 <= T && cnt < KNN) { myp[cnt] = c; cnt++; }
                    }
                }
            }
        }
    }

    float acc[NF];
#pragma unroll
    for (int f = 0; f < NF; f++) acc[f] = 0.f;
    float wsum = 0.f;
#pragma unroll
    for (int t = 0; t < KNN; t++) {
        int p = myp[t];
        float4 g = g_sorted[p];
        float4 ic = g_icov_s[p];
        int id = __float_as_int(g.w);
        float ddx = qx - g.x, ddy = qy - g.y, ddz = qz - g.z;
        float e = fmaf(ddx*ddx, ic.x, fmaf(ddy*ddy, ic.y, ddz*ddz*ic.z));
        float wgt = __expf(-0.5f * e);
        wsum += wgt;
        const float4* fp = feats4 + (size_t)id * (NF/4);
#pragma unroll
        for (int cc = 0; cc < NF/4; cc++) {
            float4 fv = fp[cc];
            acc[4*cc+0] = fmaf(wgt, fv.x, acc[4*cc+0]);
            acc[4*cc+1] = fmaf(wgt, fv.y, acc[4*cc+1]);
            acc[4*cc+2] = fmaf(wgt, fv.z, acc[4*cc+2]);
            acc[4*cc+3] = fmaf(wgt, fv.w, acc[4*cc+3]);
        }
    }
    float inv = 1.f / (wsum + 1e-8f);
    float4* o4 = (float4*)(out + (size_t)q * NF);
#pragma unroll
    for (int cc = 0; cc < NF/4; cc++)
        o4[cc] = make_float4(acc[4*cc+0]*inv, acc[4*cc+1]*inv,
                             acc[4*cc+2]*inv, acc[4*cc+3]*inv);
}

// Main: 4 lanes/query, 8 queries/warp, padded windows -> unguarded batched loads.
__global__ __launch_bounds__(128, 7)
void splash_q(const float* __restrict__ coords,
              const float4* __restrict__ feats4,
              float* __restrict__ out, int M) {
    const int gw = (blockIdx.x * blockDim.x + threadIdx.x) >> 5;
    const int lane = threadIdx.x & 31;
    const int L = lane & 3;
    const int qslot = gw * 8 + (lane >> 2);
    const bool has = qslot < M;

    const int q = g_qorder[has ? qslot : 0];
    const float qx = coords[3*q+0], qy = coords[3*q+1], qz = coords[3*q+2];
    const int cx = cell_coord(qx), cy = cell_coord(qy), cz = cell_coord(qz);
    const int cell = (cz * G + cy) * G + cx;
    const int cb = cell * CAPW;
    const int nSW = g_nsw[cell];
    const int nSWP = g_nswp[cell];
    const float wmarg = g_wmargin[cell];

    const float qq = fmaf(qx, qx, fmaf(qy, qy, qz * qz));
    const float n2x = -2.f * qx, n2y = -2.f * qy, n2z = -2.f * qz;
    const float ccx = (cx + 0.5f) * 0.125f;
    const float ccy = (cy + 0.5f) * 0.125f;
    const float ccz = (cz + 0.5f) * 0.125f;
    float rdx = qx - ccx, rdy = qy - ccy, rdz = qz - ccz;
    const float rq = sqrtf(fmaf(rdx, rdx, fmaf(rdy, rdy, rdz * rdz)));

    const bool mainable = has && nSW >= 32 && wmarg >= 0.f;

    unsigned key[KD];
#pragma unroll
    for (int t = 0; t < KD; t++) key[t] = 0xFFFFFFFFu;

    bool done = !mainable;
    for (int base = 0; !__all_sync(0xffffffffu, done); base += 32) {
        if (!done) {
            // Unguarded, front-batched loads (window padded to 32).
            float tv[8];
#pragma unroll
            for (int k = 0; k < 8; k++) {
                float4 g = __ldg(&g_winpos[cb + base + L + 4 * k]);
                tv[k] = fmaf(g.x, n2x, fmaf(g.y, n2y, fmaf(g.z, n2z, g.w)));
            }
#pragma unroll
            for (int k = 0; k < 8; k++) {
                int j = base + L + 4 * k;
                unsigned kn = (__float_as_uint(tv[k]) & ~IDXMASK) | (unsigned)j;
                if (kn < key[0]) {
                    key[0] = kn;
#pragma unroll
                    for (int s = 0; s < KD - 1; s++) {
                        unsigned a = umax(key[s], key[s+1]);
                        unsigned b = umin(key[s], key[s+1]);
                        key[s] = a; key[s+1] = b;
                    }
                }
            }
            if (base + 32 >= nSWP) done = true;
            else {
                float d16sq = __uint_as_float(key[0] & ~IDXMASK) - 3.f + qq;
                if (d16sq >= 0.f) {
                    float dn = sqrtf(d16sq) + rq;
                    if (__ldg(&g_wincd[cb + base + 32]) - BWIDTH > dn * dn)
                        done = true;
                }
            }
        }
    }

    // Pad to 16 (descending: pads first), two-stage exact quad merge.
    unsigned pe[16];
#pragma unroll
    for (int t = 0; t < 4; t++) pe[t] = 0xFFFFFFFFu;
#pragma unroll
    for (int t = 0; t < KD; t++) pe[4 + t] = key[t];

    unsigned e[16];
#pragma unroll
    for (int t = 0; t < 16; t++) {
        unsigned pp = __shfl_xor_sync(0xffffffffu, pe[15 - t], 1);
        e[t] = umin(pe[t], pp);
    }
#define CE_(i, j) { unsigned a_ = umax(e[i], e[j]); unsigned b_ = umin(e[i], e[j]); e[i] = a_; e[j] = b_; }
#pragma unroll
    for (int i = 0; i < 8; i++) CE_(i, i + 8);
#pragma unroll
    for (int hb = 0; hb < 16; hb += 8)
#pragma unroll
        for (int i = 0; i < 4; i++) CE_(hb + i, hb + i + 4);
#pragma unroll
    for (int hb = 0; hb < 16; hb += 4)
#pragma unroll
        for (int i = 0; i < 2; i++) CE_(hb + i, hb + i + 2);
#pragma unroll
    for (int i = 0; i < 16; i += 2) CE_(i, i + 1);
#undef CE_

    unsigned gk[16];
#pragma unroll
    for (int t = 0; t < 16; t++) {
        unsigned pp = __shfl_xor_sync(0xffffffffu, e[15 - t], 2);
        gk[t] = umin(e[t], pp);
    }
    unsigned mx = gk[0];
#pragma unroll
    for (int t = 1; t < 16; t++) mx = umax(mx, gk[t]);

    bool lane_ok = (key[0] >= mx);
    unsigned bal = __ballot_sync(0xffffffffu, lane_ok);
    bool quad_ok = (((bal >> (lane & ~3)) & 0xFu) == 0xFu);

    float d16sq = __uint_as_float(mx & ~IDXMASK) - 3.f + qq;
    const float h = 0.125f;
    float m = 1e30f;
    if (cx - 1 > 0)     m = fminf(m, qx - (float)(cx - 1) * h);
    if (cx + 1 < G - 1) m = fminf(m, (float)(cx + 2) * h - qx);
    if (cy - 1 > 0)     m = fminf(m, qy - (float)(cy - 1) * h);
    if (cy + 1 < G - 1) m = fminf(m, (float)(cy + 2) * h - qy);
    if (cz - 1 > 0)     m = fminf(m, qz - (float)(cz - 1) * h);
    if (cz + 1 < G - 1) m = fminf(m, (float)(cz + 2) * h - qz);

    float d16c = sqrtf(fmaxf(d16sq, 0.f));
    bool ok = mainable && quad_ok && (d16sq <= m * m)
              && ((d16c + rq) * (d16c + rq) <= wmarg);

    if (has && !ok) {
        if (L == 0) fallback_query(q, qx, qy, qz, cx, cy, cz, feats4, out);
        return;
    }
    if (!has) return;

    float acc[NF/4];
#pragma unroll
    for (int f = 0; f < NF/4; f++) acc[f] = 0.f;
    float wsum = 0.f;
#pragma unroll
    for (int t = 0; t < KNN; t++) {
        int p = (int)(gk[t] & IDXMASK);
        float4 g = __ldg(&g_winpos[cb + p]);
        float4 ic = __ldg(&g_winic[cb + p]);
        int id = __float_as_int(ic.w);
        float ddx = qx - g.x, ddy = qy - g.y, ddz = qz - g.z;
        float e2 = fmaf(ddx*ddx, ic.x, fmaf(ddy*ddy, ic.y, ddz*ddz*ic.z));
        float wgt = __expf(-0.5f * e2);
        wsum += wgt;
        const float4* fp = feats4 + (size_t)id * (NF/4) + L * 2;
        float4 f0 = __ldg(&fp[0]);
        float4 f1 = __ldg(&fp[1]);
        acc[0] = fmaf(wgt, f0.x, acc[0]);
        acc[1] = fmaf(wgt, f0.y, acc[1]);
        acc[2] = fmaf(wgt, f0.z, acc[2]);
        acc[3] = fmaf(wgt, f0.w, acc[3]);
        acc[4] = fmaf(wgt, f1.x, acc[4]);
        acc[5] = fmaf(wgt, f1.y, acc[5]);
        acc[6] = fmaf(wgt, f1.z, acc[6]);
        acc[7] = fmaf(wgt, f1.w, acc[7]);
    }
    float inv = 1.f / (wsum + 1e-8f);
    float4* o4 = (float4*)(out + (size_t)q * NF) + L * 2;
    o4[0] = make_float4(acc[0]*inv, acc[1]*inv, acc[2]*inv, acc[3]*inv);
    o4[1] = make_float4(acc[4]*inv, acc[5]*inv, acc[6]*inv, acc[7]*inv);
}

extern "C" void kernel_launch(void* const* d_in, const int* in_sizes, int n_in,
                              void* d_out, int out_size) {
    const float* coords = (const float*)d_in[0];
    const float* means  = (const float*)d_in[1];
    const float* logc   = (const float*)d_in[2];
    const float* feats  = (const float*)d_in[3];
    float* out = (float*)d_out;

    int M = in_sizes[0] / 3;
    int N = in_sizes[1] / 3;
    int mx = (M > N ? M : N);

    k_hist<<<(mx + 255) / 256, 256>>>(means, N, coords, M);
    k_scan<<<1, NC>>>();
    k_scatter<<<(mx + 255) / 256, 256>>>(means, logc, N, M);
    k_window<<<NC, 256>>>();
    int qblocks = (M * 4 + 127) / 128;
    splash_q<<<qblocks, 128>>>(coords, (const float4*)feats, out, M);
}

// round 10
// speedup vs baseline: 2.1191x; 1.0934x over previous
#include <cuda_runtime.h>
#include <math.h>
#include <float.h>

#define G 8
#define NC (G*G*G)
#define MAXN 10016
#define MAXM 32768
#define KNN 16
#define NF 32
#define CAPW 512
#define WMAX 1024
#define NBKT 32
#define KD 12
#define IDXMASK 0x1FFu
#define CDMAX 0.1055f
#define BWIDTH (CDMAX / (float)NBKT)
#define INVBW ((float)NBKT / CDMAX)

// ---- device scratch (allocation-free) ----
__device__ float4 g_sorted[MAXN];
__device__ float4 g_icov_s[MAXN];
__device__ int g_cnt[NC], g_start[NC + 1];
__device__ int g_qcnt[NC], g_qstart[NC + 1];
__device__ int g_gcell[MAXN], g_grank[MAXN];
__device__ int g_qcell[MAXM], g_qrank[MAXM];
__device__ int g_qorder[MAXM];
__device__ int g_done;                     // zero-init; reset each pass
__device__ float4 g_winpos[NC * CAPW + 32];
__device__ float4 g_winic[NC * CAPW + 32];
__device__ float  g_wincd[NC * CAPW + 32]; // +32 slack for prefetch
__device__ float  g_wmargin[NC];
__device__ int    g_nsw[NC];
__device__ int    g_nswp[NC];

__device__ __forceinline__ int cell_coord(float v) {
    int c = (int)(v * (float)G);
    return min(G - 1, max(0, c));
}

// 512-entry exclusive scan with 256 threads (2 entries/thread); zeroes src.
__device__ void scan512_zero(int* src, int* dst) {
    __shared__ int ws[8];
    int t = threadIdx.x, lane = t & 31, w = t >> 5;
    int c0 = src[2 * t], c1 = src[2 * t + 1];
    src[2 * t] = 0; src[2 * t + 1] = 0;
    int s = c0 + c1;
    int v = s;
    for (int o = 1; o < 32; o <<= 1) {
        int u = __shfl_up_sync(0xffffffffu, v, o);
        if (lane >= o) v += u;
    }
    if (lane == 31) ws[w] = v;
    __syncthreads();
    if (t < 32) {
        int p = (t < 8) ? ws[t] : 0;
        for (int o = 1; o < 8; o <<= 1) {
            int u = __shfl_up_sync(0xffffffffu, p, o);
            if (t >= o) p += u;
        }
        if (t < 8) ws[t] = p;
    }
    __syncthreads();
    int incl = v + (w ? ws[w - 1] : 0);
    int excl = incl - s;
    dst[2 * t + 1] = excl + c0;
    dst[2 * t + 2] = incl;
    if (t == 0) dst[0] = 0;
    __syncthreads();
}

// Histogram + (in the last block) both exclusive scans.
__global__ void k_hist(const float* __restrict__ means, int N,
                       const float* __restrict__ coords, int M) {
    int i = blockIdx.x * blockDim.x + threadIdx.x;
    if (i < N) {
        int c = (cell_coord(means[3*i+2]) * G + cell_coord(means[3*i+1])) * G
                + cell_coord(means[3*i+0]);
        g_gcell[i] = c;
        g_grank[i] = atomicAdd(&g_cnt[c], 1);
    }
    if (i < M) {
        int c = (cell_coord(coords[3*i+2]) * G + cell_coord(coords[3*i+1])) * G
                + cell_coord(coords[3*i+0]);
        g_qcell[i] = c;
        g_qrank[i] = atomicAdd(&g_qcnt[c], 1);
    }
    __threadfence();
    __shared__ int is_last;
    if (threadIdx.x == 0) {
        int prev = atomicAdd(&g_done, 1);
        is_last = (prev == (int)gridDim.x - 1);
    }
    __syncthreads();
    if (!is_last) return;
    if (threadIdx.x == 0) g_done = 0;
    scan512_zero(g_cnt, g_start);
    scan512_zero(g_qcnt, g_qstart);
}

__global__ void k_scatter(const float* __restrict__ means,
                          const float* __restrict__ logc, int N, int M) {
    int i = blockIdx.x * blockDim.x + threadIdx.x;
    if (i < N) {
        int pos = g_start[g_gcell[i]] + g_grank[i];
        g_sorted[pos] = make_float4(means[3*i], means[3*i+1], means[3*i+2],
                                    __int_as_float(i));
        g_icov_s[pos] = make_float4(expf(-logc[3*i]), expf(-logc[3*i+1]),
                                    expf(-logc[3*i+2]), 0.f);
    }
    if (i < M) {
        int pos = g_qstart[g_qcell[i]] + g_qrank[i];
        g_qorder[pos] = i;
    }
}

// Per-cell radially-ordered window; positions cached in smem between phases.
__global__ __launch_bounds__(256)
void k_window() {
    __shared__ float4 spos4[WMAX];
    __shared__ float  skey[WMAX];
    __shared__ int    sgid[WMAX];
    __shared__ int    cnt[NBKT], st[NBKT + 1], fil[NBKT];
    __shared__ int    rr0[9], roff[10], rcnt_s;

    const int cell = blockIdx.x, tid = threadIdx.x;
    const int cx = cell & 7, cy = (cell >> 3) & 7, cz = cell >> 6;
    const float ccx = (cx + 0.5f) * 0.125f;
    const float ccy = (cy + 0.5f) * 0.125f;
    const float ccz = (cz + 0.5f) * 0.125f;

    if (tid < NBKT) { cnt[tid] = 0; fil[tid] = 0; }

    const int x0 = max(cx - 1, 0), x1e = min(cx + 1, G - 1) + 1;
    if (tid == 0) {
        int rc = 0, n0 = 0;
        for (int z = max(cz - 1, 0); z <= min(cz + 1, G - 1); ++z) {
            for (int y = max(cy - 1, 0); y <= min(cy + 1, G - 1); ++y) {
                int base = (z * G + y) * G;
                int r0 = g_start[base + x0];
                int len = g_start[base + x1e] - r0;
                rr0[rc] = r0; roff[rc] = n0;
                n0 += len; rc++;
            }
        }
        roff[rc] = n0;
        rcnt_s = rc;
    }
    __syncthreads();

    const int rcnt = rcnt_s;
    const int n = roff[rcnt];
    const bool ovf = (n > WMAX);

    if (!ovf) {
        for (int i = tid; i < n; i += 256) {
            int k = 0;
#pragma unroll
            for (int kk = 1; kk < 9; kk++)
                if (kk < rcnt && i >= roff[kk]) k = kk;
            int src = rr0[k] + (i - roff[k]);
            float4 g = g_sorted[src];
            float dx = g.x - ccx, dy = g.y - ccy, dz = g.z - ccz;
            float cd = fmaf(dx, dx, fmaf(dy, dy, dz * dz));
            spos4[i] = g;
            skey[i] = cd;
            sgid[i] = src;
            atomicAdd(&cnt[min(NBKT - 1, (int)(cd * INVBW))], 1);
        }
    }
    __syncthreads();

    if (tid < 32) {
        int v = cnt[tid];
        for (int o = 1; o < 32; o <<= 1) {
            int u = __shfl_up_sync(0xffffffffu, v, o);
            if (tid >= o) v += u;
        }
        st[tid + 1] = v;
        if (tid == 0) st[0] = 0;
    }
    __syncthreads();

    int nsw = min(n, CAPW);
    if (ovf) nsw = 0;
    const int nswp = min(CAPW, (nsw + 31) & ~31);

    if (tid == 0) {
        float marg = 1e30f;
        if (ovf) marg = -1.f;
        else if (n > CAPW) {
            int t = 0;
            while (t < NBKT && st[t + 1] <= CAPW) t++;
            marg = (float)t * BWIDTH;
        }
        g_wmargin[cell] = marg;
        g_nsw[cell] = nsw;
        g_nswp[cell] = nswp;
    }
    __syncthreads();

    if (!ovf) {
        for (int i = tid; i < n; i += 256) {
            float cd = skey[i];
            int b = min(NBKT - 1, (int)(cd * INVBW));
            int pos = st[b] + atomicAdd(&fil[b], 1);
            if (pos < CAPW) {
                float4 gp = spos4[i];
                float m2 = fmaf(gp.x, gp.x, fmaf(gp.y, gp.y, gp.z * gp.z)) + 3.f;
                g_winpos[cell * CAPW + pos] = make_float4(gp.x, gp.y, gp.z, m2);
                float4 ic = g_icov_s[sgid[i]];
                g_winic[cell * CAPW + pos] = make_float4(ic.x, ic.y, ic.z, gp.w);
                g_wincd[cell * CAPW + pos] = cd;
            }
        }
        for (int i = nsw + tid; i < nswp; i += 256) {
            g_winpos[cell * CAPW + i] = make_float4(64.f, 64.f, 64.f,
                                                    3.f * 64.f * 64.f + 3.f);
            g_winic[cell * CAPW + i] = make_float4(0.f, 0.f, 0.f,
                                                   __int_as_float(0));
            g_wincd[cell * CAPW + i] = 1e30f;
        }
    }
}

// Exact per-query fallback (rare).
__device__ __noinline__ void fallback_query(int q, float qx, float qy, float qz,
                                            int cx, int cy, int cz,
                                            const float4* __restrict__ feats4,
                                            float* __restrict__ out) {
    const float h = 1.0f / (float)G;
    float bd[KNN];
#pragma unroll
    for (int t = 0; t < KNN; t++) bd[t] = FLT_MAX;

    int rfin = 1;
    for (int r = 1; r <= G; ++r) {
        rfin = r;
        for (int dz = -r; dz <= r; ++dz) {
            int z = cz + dz; if ((unsigned)z >= G) continue;
            for (int dy = -r; dy <= r; ++dy) {
                int y = cy + dy; if ((unsigned)y >= G) continue;
                bool edge = (dz == -r) | (dz == r) | (dy == -r) | (dy == r);
                int step = (r > 1 && !edge) ? 2 * r : 1;
                for (int dx = -r; dx <= r; dx += step) {
                    int x = cx + dx; if ((unsigned)x >= G) continue;
                    int cid = (z * G + y) * G + x;
                    int c0 = g_start[cid], c1 = g_start[cid + 1];
                    for (int c = c0; c < c1; ++c) {
                        float4 g = g_sorted[c];
                        float ddx = qx - g.x, ddy = qy - g.y, ddz = qz - g.z;
                        float d2 = fmaf(ddx, ddx, fmaf(ddy, ddy, ddz * ddz));
                        if (d2 < bd[0]) {
                            bd[0] = d2;
#pragma unroll
                            for (int t = 0; t < KNN - 1; t++) {
                                float a = fmaxf(bd[t], bd[t+1]);
                                float b = fminf(bd[t], bd[t+1]);
                                bd[t] = a; bd[t+1] = b;
                            }
                        }
                    }
                }
            }
        }
        float m = 1e30f;
        if (cx - r > 0)     m = fminf(m, qx - (float)(cx - r) * h);
        if (cx + r < G - 1) m = fminf(m, (float)(cx + r + 1) * h - qx);
        if (cy - r > 0)     m = fminf(m, qy - (float)(cy - r) * h);
        if (cy + r < G - 1) m = fminf(m, (float)(cy + r + 1) * h - qy);
        if (cz - r > 0)     m = fminf(m, qz - (float)(cz - r) * h);
        if (cz + r < G - 1) m = fminf(m, (float)(cz + r + 1) * h - qz);
        if (bd[0] <= m * m) break;
    }
    const float T = bd[0];

    int myp[KNN];
#pragma unroll
    for (int t = 0; t < KNN; t++) myp[t] = 0;
    int cnt = 0;
    {
        const int r = rfin;
        for (int dz = -r; dz <= r; ++dz) {
            int z = cz + dz; if ((unsigned)z >= G) continue;
            for (int dy = -r; dy <= r; ++dy) {
                int y = cy + dy; if ((unsigned)y >= G) continue;
                for (int dx = -r; dx <= r; ++dx) {
                    int x = cx + dx; if ((unsigned)x >= G) continue;
                    int cid = (z * G + y) * G + x;
                    int c0 = g_start[cid], c1 = g_start[cid + 1];
                    for (int c = c0; c < c1; ++c) {
                        float4 g = g_sorted[c];
                        float ddx = qx - g.x, ddy = qy - g.y, ddz = qz - g.z;
                        float d2 = fmaf(ddx, ddx, fmaf(ddy, ddy, ddz * ddz));
                        if (d2 <= T && cnt < KNN) { myp[cnt] = c; cnt++; }
                    }
                }
            }
        }
    }

    float acc[NF];
#pragma unroll
    for (int f = 0; f < NF; f++) acc[f] = 0.f;
    float wsum = 0.f;
#pragma unroll
    for (int t = 0; t < KNN; t++) {
        int p = myp[t];
        float4 g = g_sorted[p];
        float4 ic = g_icov_s[p];
        int id = __float_as_int(g.w);
        float ddx = qx - g.x, ddy = qy - g.y, ddz = qz - g.z;
        float e = fmaf(ddx*ddx, ic.x, fmaf(ddy*ddy, ic.y, ddz*ddz*ic.z));
        float wgt = __expf(-0.5f * e);
        wsum += wgt;
        const float4* fp = feats4 + (size_t)id * (NF/4);
#pragma unroll
        for (int cc = 0; cc < NF/4; cc++) {
            float4 fv = fp[cc];
            acc[4*cc+0] = fmaf(wgt, fv.x, acc[4*cc+0]);
            acc[4*cc+1] = fmaf(wgt, fv.y, acc[4*cc+1]);
            acc[4*cc+2] = fmaf(wgt, fv.z, acc[4*cc+2]);
            acc[4*cc+3] = fmaf(wgt, fv.w, acc[4*cc+3]);
        }
    }
    float inv = 1.f / (wsum + 1e-8f);
    float4* o4 = (float4*)(out + (size_t)q * NF);
#pragma unroll
    for (int cc = 0; cc < NF/4; cc++)
        o4[cc] = make_float4(acc[4*cc+0]*inv, acc[4*cc+1]*inv,
                             acc[4*cc+2]*inv, acc[4*cc+3]*inv);
}

// Main: 4 lanes/query, 8 queries/warp, padded windows, prefetched early exit.
__global__ __launch_bounds__(128, 7)
void splash_q(const float* __restrict__ coords,
              const float4* __restrict__ feats4,
              float* __restrict__ out, int M) {
    const int gw = (blockIdx.x * blockDim.x + threadIdx.x) >> 5;
    const int lane = threadIdx.x & 31;
    const int L = lane & 3;
    const int qslot = gw * 8 + (lane >> 2);
    const bool has = qslot < M;

    const int q = g_qorder[has ? qslot : 0];
    const float qx = coords[3*q+0], qy = coords[3*q+1], qz = coords[3*q+2];
    const int cx = cell_coord(qx), cy = cell_coord(qy), cz = cell_coord(qz);
    const int cell = (cz * G + cy) * G + cx;
    const int cb = cell * CAPW;
    const int nSW = g_nsw[cell];
    const int nSWP = g_nswp[cell];
    const float wmarg = g_wmargin[cell];

    const float qq = fmaf(qx, qx, fmaf(qy, qy, qz * qz));
    const float n2x = -2.f * qx, n2y = -2.f * qy, n2z = -2.f * qz;
    const float ccx = (cx + 0.5f) * 0.125f;
    const float ccy = (cy + 0.5f) * 0.125f;
    const float ccz = (cz + 0.5f) * 0.125f;
    float rdx = qx - ccx, rdy = qy - ccy, rdz = qz - ccz;
    const float rq = sqrtf(fmaf(rdx, rdx, fmaf(rdy, rdy, rdz * rdz)));

    const bool mainable = has && nSW >= 32 && wmarg >= 0.f;

    unsigned key[KD];
#pragma unroll
    for (int t = 0; t < KD; t++) key[t] = 0xFFFFFFFFu;

    bool done = !mainable;
    for (int base = 0; !__all_sync(0xffffffffu, done); base += 32) {
        if (!done) {
            // Prefetch next chunk's exit key; overlaps candidate loads.
            float ncd = __ldg(&g_wincd[cb + base + 32]);
            float tv[8];
#pragma unroll
            for (int k = 0; k < 8; k++) {
                float4 g = __ldg(&g_winpos[cb + base + L + 4 * k]);
                tv[k] = fmaf(g.x, n2x, fmaf(g.y, n2y, fmaf(g.z, n2z, g.w)));
            }
#pragma unroll
            for (int k = 0; k < 8; k++) {
                int j = base + L + 4 * k;
                unsigned kn = (__float_as_uint(tv[k]) & ~IDXMASK) | (unsigned)j;
                if (kn < key[0]) {
                    key[0] = kn;
#pragma unroll
                    for (int s = 0; s < KD - 1; s++) {
                        unsigned a = umax(key[s], key[s+1]);
                        unsigned b = umin(key[s], key[s+1]);
                        key[s] = a; key[s+1] = b;
                    }
                }
            }
            if (base + 32 >= nSWP) done = true;
            else {
                float d16sq = __uint_as_float(key[0] & ~IDXMASK) - 3.f + qq;
                if (d16sq >= 0.f) {
                    float dn = sqrtf(d16sq) + rq;
                    if (ncd - BWIDTH > dn * dn) done = true;
                }
            }
        }
    }

    // Two-stage exact quad merge (pads inlined: slots 0..3 are +inf).
#define PK_(i) ((i) < 4 ? 0xFFFFFFFFu : key[(i) - 4])
    unsigned e[16];
#pragma unroll
    for (int t = 0; t < 16; t++) {
        unsigned pp = __shfl_xor_sync(0xffffffffu, PK_(15 - t), 1);
        e[t] = umin(PK_(t), pp);
    }
#undef PK_
#define CE_(i, j) { unsigned a_ = umax(e[i], e[j]); unsigned b_ = umin(e[i], e[j]); e[i] = a_; e[j] = b_; }
#pragma unroll
    for (int i = 0; i < 8; i++) CE_(i, i + 8);
#pragma unroll
    for (int hb = 0; hb < 16; hb += 8)
#pragma unroll
        for (int i = 0; i < 4; i++) CE_(hb + i, hb + i + 4);
#pragma unroll
    for (int hb = 0; hb < 16; hb += 4)
#pragma unroll
        for (int i = 0; i < 2; i++) CE_(hb + i, hb + i + 2);
#pragma unroll
    for (int i = 0; i < 16; i += 2) CE_(i, i + 1);
#undef CE_

    unsigned gk[16];
#pragma unroll
    for (int t = 0; t < 16; t++) {
        unsigned pp = __shfl_xor_sync(0xffffffffu, e[15 - t], 2);
        gk[t] = umin(e[t], pp);
    }
    unsigned mx = gk[0];
#pragma unroll
    for (int t = 1; t < 16; t++) mx = umax(mx, gk[t]);

    bool lane_ok = (key[0] >= mx);
    unsigned bal = __ballot_sync(0xffffffffu, lane_ok);
    bool quad_ok = (((bal >> (lane & ~3)) & 0xFu) == 0xFu);

    float d16sq = __uint_as_float(mx & ~IDXMASK) - 3.f + qq;
    const float h = 0.125f;
    float m = 1e30f;
    if (cx - 1 > 0)     m = fminf(m, qx - (float)(cx - 1) * h);
    if (cx + 1 < G - 1) m = fminf(m, (float)(cx + 2) * h - qx);
    if (cy - 1 > 0)     m = fminf(m, qy - (float)(cy - 1) * h);
    if (cy + 1 < G - 1) m = fminf(m, (float)(cy + 2) * h - qy);
    if (cz - 1 > 0)     m = fminf(m, qz - (float)(cz - 1) * h);
    if (cz + 1 < G - 1) m = fminf(m, (float)(cz + 2) * h - qz);

    float d16c = sqrtf(fmaxf(d16sq, 0.f));
    bool ok = mainable && quad_ok && (d16sq <= m * m)
              && ((d16c + rq) * (d16c + rq) <= wmarg);

    if (has && !ok) {
        if (L == 0) fallback_query(q, qx, qy, qz, cx, cy, cz, feats4, out);
        return;
    }
    if (!has) return;

    float acc[NF/4];
#pragma unroll
    for (int f = 0; f < NF/4; f++) acc[f] = 0.f;
    float wsum = 0.f;
#pragma unroll
    for (int t = 0; t < KNN; t++) {
        int p = (int)(gk[t] & IDXMASK);
        float4 g = __ldg(&g_winpos[cb + p]);
        float4 ic = __ldg(&g_winic[cb + p]);
        int id = __float_as_int(ic.w);
        float ddx = qx - g.x, ddy = qy - g.y, ddz = qz - g.z;
        float e2 = fmaf(ddx*ddx, ic.x, fmaf(ddy*ddy, ic.y, ddz*ddz*ic.z));
        float wgt = __expf(-0.5f * e2);
        wsum += wgt;
        const float4* fp = feats4 + (size_t)id * (NF/4) + L * 2;
        float4 f0 = __ldg(&fp[0]);
        float4 f1 = __ldg(&fp[1]);
        acc[0] = fmaf(wgt, f0.x, acc[0]);
        acc[1] = fmaf(wgt, f0.y, acc[1]);
        acc[2] = fmaf(wgt, f0.z, acc[2]);
        acc[3] = fmaf(wgt, f0.w, acc[3]);
        acc[4] = fmaf(wgt, f1.x, acc[4]);
        acc[5] = fmaf(wgt, f1.y, acc[5]);
        acc[6] = fmaf(wgt, f1.z, acc[6]);
        acc[7] = fmaf(wgt, f1.w, acc[7]);
    }
    float inv = 1.f / (wsum + 1e-8f);
    float4* o4 = (float4*)(out + (size_t)q * NF) + L * 2;
    o4[0] = make_float4(acc[0]*inv, acc[1]*inv, acc[2]*inv, acc[3]*inv);
    o4[1] = make_float4(acc[4]*inv, acc[5]*inv, acc[6]*inv, acc[7]*inv);
}

extern "C" void kernel_launch(void* const* d_in, const int* in_sizes, int n_in,
                              void* d_out, int out_size) {
    const float* coords = (const float*)d_in[0];
    const float* means  = (const float*)d_in[1];
    const float* logc   = (const float*)d_in[2];
    const float* feats  = (const float*)d_in[3];
    float* out = (float*)d_out;

    int M = in_sizes[0] / 3;
    int N = in_sizes[1] / 3;
    int mx = (M > N ? M : N);

    k_hist<<<(mx + 255) / 256, 256>>>(means, N, coords, M);
    k_scatter<<<(mx + 255) / 256, 256>>>(means, logc, N, M);
    k_window<<<NC, 256>>>();
    int qblocks = (M * 4 + 127) / 128;
    splash_q<<<qblocks, 128>>>(coords, (const float4*)feats, out, M);
}